// round 9
// baseline (speedup 1.0000x reference)
#include <cuda_runtime.h>

#define NN 100000
#define EE 1200000
#define GG 128
#define OUTC 320        // 64*(4+1)
#define ROWS 64         // rows per GEMM block
#define GT 128          // threads per GEMM block
#define SMEM_G 33536    // (4096 + 4096 + 64 + 64 + 64) floats * 4
#define NB 98           // scan blocks = ceil(NN/1024)

typedef unsigned long long u64;

// ---------------- scratch (static __device__, no allocation) ----------------
__device__ __align__(128) float g_h[NN * 64];
__device__ __align__(128) float g_z1[NN * 64];
__device__ int   g_esrc[EE];
__device__ int   g_rowptr[NN + 1];
__device__ int   g_cursor[NN];
__device__ int   g_deg[NN];
__device__ int   g_bsum[NB];
__device__ float g_pool[GG * OUTC];
__device__ int   g_cnt[GG];
__device__ float g_bnsum[4 * 64];
__device__ float g_bnsq[4 * 64];

// ---------------- packed f32x2 helpers ----------------
__device__ __forceinline__ u64 pack2(float x, float y) {
    u64 r; asm("mov.b64 %0, {%1, %2};" : "=l"(r) : "f"(x), "f"(y)); return r;
}
__device__ __forceinline__ void ffma2(u64& d, u64 a, u64 b) {
    asm("fma.rn.f32x2 %0, %1, %2, %0;" : "+l"(d) : "l"(a), "l"(b));
}
__device__ __forceinline__ float2 unpack2(u64 v) {
    float2 f; asm("mov.b64 {%0, %1}, %2;" : "=f"(f.x), "=f"(f.y) : "l"(v)); return f;
}

// ---------------- per-graph node counts ----------------
__global__ void count_kernel(const int* __restrict__ batch) {
    int i = blockIdx.x * 256 + threadIdx.x;
    if (i < NN) atomicAdd(&g_cnt[batch[i]], 1);
}

// ---------------- CSR build ----------------
__global__ void deg_kernel(const int* __restrict__ ei) {
    int e = blockIdx.x * 256 + threadIdx.x;
    if (e < EE) atomicAdd(&g_deg[ei[EE + e]], 1);
}

__global__ void scan1_kernel() {
    __shared__ int s[1024];
    int t = threadIdx.x;
    int i = blockIdx.x * 1024 + t;
    int x = (i < NN) ? g_deg[i] : 0;
    s[t] = x;
    __syncthreads();
#pragma unroll
    for (int off = 1; off < 1024; off <<= 1) {
        int v = (t >= off) ? s[t - off] : 0;
        __syncthreads();
        s[t] += v;
        __syncthreads();
    }
    if (i < NN) g_rowptr[i] = s[t] - x;      // exclusive, partial
    if (t == 1023) g_bsum[blockIdx.x] = s[1023];
}

__global__ void scan2_kernel() {
    __shared__ int s[128];
    int t = threadIdx.x;
    int x = (t < NB) ? g_bsum[t] : 0;
    s[t] = x;
    __syncthreads();
#pragma unroll
    for (int off = 1; off < 128; off <<= 1) {
        int v = (t >= off) ? s[t - off] : 0;
        __syncthreads();
        s[t] += v;
        __syncthreads();
    }
    if (t < NB) g_bsum[t] = s[t] - x;        // exclusive
}

__global__ void scan3_kernel() {
    int i = blockIdx.x * 256 + threadIdx.x;
    if (i < NN) {
        int v = g_rowptr[i] + g_bsum[i >> 10];
        g_rowptr[i] = v;
        g_cursor[i] = v;
    }
    if (i == 0) g_rowptr[NN] = EE;
}

__global__ void fill_kernel(const int* __restrict__ ei) {
    int e = blockIdx.x * 256 + threadIdx.x;
    if (e < EE) {
        int dst = ei[EE + e];
        int pos = atomicAdd(&g_cursor[dst], 1);
        g_esrc[pos] = ei[e];
    }
}

// Zs layout: row r at floats [r*64, r*64+64); col k stored at slot
// ((k + 4*(r>>2)) & 63). Rotation multiple of 4 floats keeps float4 alignment;
// the 4 row-groups within a warp land on banks 4 apart -> conflict-free.

// ---------------- GEMM1 (fused gather): z1 = (h + A h) @ W1 + b1, + BN stats ----
// 64 rows x 64 cols per block, 128 threads, thread tile = 4 rows x 8 cols
__global__ __launch_bounds__(GT, 6) void gemm1_kernel(const float* __restrict__ W,
                                                      const float* __restrict__ b,
                                                      int layer) {
    extern __shared__ float smp[];
    float* Ws = smp;          // 4096 floats
    float* Zs = smp + 4096;   // 4096 floats
    int t = threadIdx.x;
    int row0 = blockIdx.x * ROWS;

    const float4* Wg = (const float4*)W;
    float4* Ws4 = (float4*)Ws;
#pragma unroll
    for (int i = 0; i < 8; i++) Ws4[t + i * GT] = Wg[t + i * GT];

    // fused CSR gather: 16 consecutive threads cover one row's 16 float4 chunks
    const float4* h4 = (const float4*)g_h;
#pragma unroll
    for (int i = 0; i < 8; i++) {
        int e = t + i * GT;                // 64*16 = 1024 (row, chunk) pairs
        int r = e >> 4, c4 = e & 15;
        int gr = row0 + r;
        float4 v = make_float4(0.f, 0.f, 0.f, 0.f);
        if (gr < NN) {
            v = h4[(size_t)gr * 16 + c4];
            int beg = g_rowptr[gr], end = g_rowptr[gr + 1];
            for (int p = beg; p < end; p++) {
                int s = g_esrc[p];
                float4 a = h4[(size_t)s * 16 + c4];
                v.x += a.x; v.y += a.y; v.z += a.z; v.w += a.w;
            }
        }
        ((float4*)(Zs + r * 64))[(c4 + (r >> 2)) & 15] = v;
    }
    __syncthreads();

    int cw = t & 7;            // col group: cols cw*8 .. cw*8+7
    int g  = t >> 3;           // row group 0..15: rows g*4 .. g*4+3
    int rowb = g * 4;
    u64 acc[4][4];
#pragma unroll
    for (int c = 0; c < 4; c++) {
        u64 bp = pack2(b[cw * 8 + c * 2], b[cw * 8 + c * 2 + 1]);
#pragma unroll
        for (int j = 0; j < 4; j++) acc[j][c] = bp;
    }

    const ulonglong2* Wsu = (const ulonglong2*)Ws;   // 16 units per k-row
#pragma unroll 8
    for (int k = 0; k < 64; k++) {
        ulonglong2 wa = Wsu[k * 16 + cw * 2];
        ulonglong2 wb = Wsu[k * 16 + cw * 2 + 1];
        int kk = (k + 4 * g) & 63;
#pragma unroll
        for (int j = 0; j < 4; j++) {
            float z = Zs[(rowb + j) * 64 + kk];
            u64 zz = pack2(z, z);
            ffma2(acc[j][0], zz, wa.x);
            ffma2(acc[j][1], zz, wa.y);
            ffma2(acc[j][2], zz, wb.x);
            ffma2(acc[j][3], zz, wb.y);
        }
    }
    __syncthreads();   // done reading Zs; reuse it for outputs

#pragma unroll
    for (int j = 0; j < 4; j++) {
        int r = rowb + j;
        int gr = row0 + r;
        float2 p0 = unpack2(acc[j][0]), p1 = unpack2(acc[j][1]);
        float2 p2 = unpack2(acc[j][2]), p3 = unpack2(acc[j][3]);
        float4 o0 = make_float4(p0.x, p0.y, p1.x, p1.y);
        float4 o1 = make_float4(p2.x, p2.y, p3.x, p3.y);
        if (gr < NN) {
            float4* og = (float4*)(g_z1 + (size_t)gr * 64 + cw * 8);
            og[0] = o0; og[1] = o1;
        } else {
            o0 = make_float4(0.f, 0.f, 0.f, 0.f);
            o1 = o0;
        }
        float4* zr = (float4*)(Zs + r * 64);
        zr[(cw * 2 + g) & 15]     = o0;
        zr[(cw * 2 + 1 + g) & 15] = o1;
    }
    __syncthreads();

    // BN stats: 128 threads, 2 row-halves x 64 cols
    {
        int col = t & 63, half = t >> 6;
        float s = 0.f, q = 0.f;
#pragma unroll 8
        for (int r = half * 32; r < half * 32 + 32; r++) {
            float v = Zs[r * 64 + ((col + 4 * (r >> 2)) & 63)];
            s += v;
            q += v * v;
        }
        atomicAdd(&g_bnsum[layer * 64 + col], s);
        atomicAdd(&g_bnsq[layer * 64 + col], q);
    }
}

// ---------------- GEMM2: h = relu(bn(z1)) @ W2 + b2, plus mean-pool ----------------
// BN=false is the embedding GEMM: h = x @ W_emb + b_emb
template <bool BN>
__global__ __launch_bounds__(GT, 6) void gemm2_kernel(const float* __restrict__ in,
                             const float* __restrict__ W, const float* __restrict__ b,
                             const float* __restrict__ gamma, const float* __restrict__ beta,
                             const int* __restrict__ batch, int pool_off, int layer) {
    extern __shared__ float smp[];
    float* Ws = smp;            // 4096
    float* Zs = smp + 4096;     // 4096
    float* sc = smp + 8192;     // 64
    float* sh = smp + 8256;     // 64
    int*   sb = (int*)(smp + 8320);  // 64
    int t = threadIdx.x;
    int row0 = blockIdx.x * ROWS;

    if (t < ROWS) {
        int gr = row0 + t;
        sb[t] = (gr < NN) ? batch[gr] : -1;
    }
    if (t < 64 && BN) {
        float mu = g_bnsum[layer * 64 + t] * (1.f / NN);
        float var = g_bnsq[layer * 64 + t] * (1.f / NN) - mu * mu;
        float rs = rsqrtf(var + 1e-5f);
        float s = gamma[t] * rs;
        sc[t] = s;
        sh[t] = beta[t] - mu * s;
    }
    const float4* Wg = (const float4*)W;
    float4* Ws4 = (float4*)Ws;
#pragma unroll
    for (int i = 0; i < 8; i++) Ws4[t + i * GT] = Wg[t + i * GT];
    __syncthreads();

#pragma unroll
    for (int i = 0; i < 8; i++) {
        int e = t + i * GT;
        int r = e >> 4, c4 = e & 15;
        int gr = row0 + r;
        float4 v = make_float4(0.f, 0.f, 0.f, 0.f);
        if (gr < NN) {
            v = ((const float4*)in)[(size_t)gr * 16 + c4];
            if (BN) {
                int k = c4 * 4;
                v.x = fmaxf(v.x * sc[k]     + sh[k],     0.f);
                v.y = fmaxf(v.y * sc[k + 1] + sh[k + 1], 0.f);
                v.z = fmaxf(v.z * sc[k + 2] + sh[k + 2], 0.f);
                v.w = fmaxf(v.w * sc[k + 3] + sh[k + 3], 0.f);
            }
        }
        ((float4*)(Zs + r * 64))[(c4 + (r >> 2)) & 15] = v;
    }
    __syncthreads();

    int cw = t & 7;
    int g  = t >> 3;
    int rowb = g * 4;
    u64 acc[4][4];
#pragma unroll
    for (int c = 0; c < 4; c++) {
        u64 bp = pack2(b[cw * 8 + c * 2], b[cw * 8 + c * 2 + 1]);
#pragma unroll
        for (int j = 0; j < 4; j++) acc[j][c] = bp;
    }

    const ulonglong2* Wsu = (const ulonglong2*)Ws;
#pragma unroll 8
    for (int k = 0; k < 64; k++) {
        ulonglong2 wa = Wsu[k * 16 + cw * 2];
        ulonglong2 wb = Wsu[k * 16 + cw * 2 + 1];
        int kk = (k + 4 * g) & 63;
#pragma unroll
        for (int j = 0; j < 4; j++) {
            float z = Zs[(rowb + j) * 64 + kk];
            u64 zz = pack2(z, z);
            ffma2(acc[j][0], zz, wa.x);
            ffma2(acc[j][1], zz, wa.y);
            ffma2(acc[j][2], zz, wb.x);
            ffma2(acc[j][3], zz, wb.y);
        }
    }
    __syncthreads();

#pragma unroll
    for (int j = 0; j < 4; j++) {
        int r = rowb + j;
        int gr = row0 + r;
        float2 p0 = unpack2(acc[j][0]), p1 = unpack2(acc[j][1]);
        float2 p2 = unpack2(acc[j][2]), p3 = unpack2(acc[j][3]);
        float4 o0 = make_float4(p0.x, p0.y, p1.x, p1.y);
        float4 o1 = make_float4(p2.x, p2.y, p3.x, p3.y);
        if (gr < NN) {
            float4* og = (float4*)(g_h + (size_t)gr * 64 + cw * 8);
            og[0] = o0; og[1] = o1;
        } else {
            o0 = make_float4(0.f, 0.f, 0.f, 0.f);
            o1 = o0;
        }
        float4* zr = (float4*)(Zs + r * 64);
        zr[(cw * 2 + g) & 15]     = o0;
        zr[(cw * 2 + 1 + g) & 15] = o1;
    }
    __syncthreads();

    // segmented mean-pool accumulation (batch sorted -> few runs per block)
    if (t < 64) {
        float s = 0.f;
        int cur = sb[0];
        for (int r = 0; r < ROWS; r++) {
            int g2 = sb[r];
            if (g2 != cur) {
                if (cur >= 0) atomicAdd(&g_pool[cur * OUTC + pool_off + t], s);
                s = 0.f;
                cur = g2;
            }
            s += Zs[r * 64 + ((t + 4 * (r >> 2)) & 63)];
        }
        if (cur >= 0) atomicAdd(&g_pool[cur * OUTC + pool_off + t], s);
    }
}

__global__ void finalize_kernel(float* __restrict__ out) {
    int i = blockIdx.x * 256 + threadIdx.x;
    if (i < GG * OUTC) {
        int g = i / OUTC;
        float c = (float)max(g_cnt[g], 1);
        out[i] = g_pool[i] / c;
    }
}

// ---------------- host ----------------
extern "C" void kernel_launch(void* const* d_in, const int* in_sizes, int n_in,
                              void* d_out, int out_size) {
    const float* x     = (const float*)d_in[0];
    const int*   ei    = (const int*)d_in[1];
    const int*   batch = (const int*)d_in[2];
    const float* W_emb = (const float*)d_in[3];
    const float* b_emb = (const float*)d_in[4];
    const float* W1    = (const float*)d_in[5];
    const float* b1    = (const float*)d_in[6];
    const float* gamma = (const float*)d_in[7];
    const float* beta  = (const float*)d_in[8];
    const float* W2    = (const float*)d_in[9];
    const float* b2    = (const float*)d_in[10];
    float* out = (float*)d_out;

    cudaFuncSetAttribute(gemm1_kernel, cudaFuncAttributeMaxDynamicSharedMemorySize, SMEM_G);
    cudaFuncSetAttribute(gemm2_kernel<false>, cudaFuncAttributeMaxDynamicSharedMemorySize, SMEM_G);
    cudaFuncSetAttribute(gemm2_kernel<true>, cudaFuncAttributeMaxDynamicSharedMemorySize, SMEM_G);

    void *p_pool, *p_cnt, *p_deg, *p_bnsum, *p_bnsq, *p_z1;
    cudaGetSymbolAddress(&p_pool, g_pool);
    cudaGetSymbolAddress(&p_cnt, g_cnt);
    cudaGetSymbolAddress(&p_deg, g_deg);
    cudaGetSymbolAddress(&p_bnsum, g_bnsum);
    cudaGetSymbolAddress(&p_bnsq, g_bnsq);
    cudaGetSymbolAddress(&p_z1, g_z1);

    cudaMemsetAsync(p_pool, 0, GG * OUTC * sizeof(float), 0);
    cudaMemsetAsync(p_cnt, 0, GG * sizeof(int), 0);
    cudaMemsetAsync(p_deg, 0, NN * sizeof(int), 0);
    cudaMemsetAsync(p_bnsum, 0, 4 * 64 * sizeof(float), 0);
    cudaMemsetAsync(p_bnsq, 0, 4 * 64 * sizeof(float), 0);

    count_kernel<<<(NN + 255) / 256, 256>>>(batch);

    // ---- CSR build (edge structure constant across layers) ----
    deg_kernel<<<(EE + 255) / 256, 256>>>(ei);
    scan1_kernel<<<NB, 1024>>>();
    scan2_kernel<<<1, 128>>>();
    scan3_kernel<<<(NN + 255) / 256, 256>>>();
    fill_kernel<<<(EE + 255) / 256, 256>>>(ei);

    const int GB = (NN + ROWS - 1) / ROWS;  // 1563 row-tiles

    // embedding GEMM + pool into columns [0,64)
    gemm2_kernel<false><<<GB, GT, SMEM_G>>>(x, W_emb, b_emb, nullptr, nullptr, batch, 0, 0);

    for (int l = 0; l < 4; l++) {
        gemm1_kernel<<<GB, GT, SMEM_G>>>(W1 + l * 4096, b1 + l * 64, l);
        gemm2_kernel<true><<<GB, GT, SMEM_G>>>((const float*)p_z1, W2 + l * 4096, b2 + l * 64,
                                        gamma + l * 64, beta + l * 64, batch,
                                        (l + 1) * 64, l);
    }

    finalize_kernel<<<(GG * OUTC + 255) / 256, 256>>>(out);
}

// round 10
// speedup vs baseline: 1.0469x; 1.0469x over previous
#include <cuda_runtime.h>

#define NN 100000
#define EE 1200000
#define GG 128
#define OUTC 320        // 64*(4+1)
#define ROWS 64         // rows per GEMM block
#define GT 128          // threads per GEMM block
#define SMEM_G 33536    // (4096 + 4096 + 64 + 64 + 64) floats * 4
#define NB 98           // scan blocks = ceil(NN/1024)

typedef unsigned long long u64;

// ---------------- scratch (static __device__, no allocation) ----------------
__device__ __align__(128) float g_h[NN * 64];
__device__ __align__(128) float g_agg[NN * 64];
__device__ __align__(128) float g_z1[NN * 64];
__device__ int   g_esrc[EE];
__device__ int   g_rowptr[NN + 1];
__device__ int   g_cursor[NN];
__device__ int   g_deg[NN];
__device__ int   g_bsum[NB];
__device__ float g_pool[GG * OUTC];
__device__ int   g_cnt[GG];
__device__ float g_bnsum[4 * 64];
__device__ float g_bnsq[4 * 64];

// ---------------- packed f32x2 helpers ----------------
__device__ __forceinline__ u64 pack2(float x, float y) {
    u64 r; asm("mov.b64 %0, {%1, %2};" : "=l"(r) : "f"(x), "f"(y)); return r;
}
__device__ __forceinline__ void ffma2(u64& d, u64 a, u64 b) {
    asm("fma.rn.f32x2 %0, %1, %2, %0;" : "+l"(d) : "l"(a), "l"(b));
}
__device__ __forceinline__ float2 unpack2(u64 v) {
    float2 f; asm("mov.b64 {%0, %1}, %2;" : "=f"(f.x), "=f"(f.y) : "l"(v)); return f;
}

// ---------------- fused: per-graph node counts + in-degree histogram ----------
__global__ void count_deg_kernel(const int* __restrict__ batch,
                                 const int* __restrict__ ei) {
    int i = blockIdx.x * 256 + threadIdx.x;
    if (i < NN) atomicAdd(&g_cnt[batch[i]], 1);
    if (i < EE) atomicAdd(&g_deg[ei[EE + i]], 1);
}

// ---------------- CSR build ----------------
__global__ void scan1_kernel() {
    __shared__ int s[1024];
    int t = threadIdx.x;
    int i = blockIdx.x * 1024 + t;
    int x = (i < NN) ? g_deg[i] : 0;
    s[t] = x;
    __syncthreads();
#pragma unroll
    for (int off = 1; off < 1024; off <<= 1) {
        int v = (t >= off) ? s[t - off] : 0;
        __syncthreads();
        s[t] += v;
        __syncthreads();
    }
    if (i < NN) g_rowptr[i] = s[t] - x;      // exclusive, partial
    if (t == 1023) g_bsum[blockIdx.x] = s[1023];
}

__global__ void scan2_kernel() {
    __shared__ int s[128];
    int t = threadIdx.x;
    int x = (t < NB) ? g_bsum[t] : 0;
    s[t] = x;
    __syncthreads();
#pragma unroll
    for (int off = 1; off < 128; off <<= 1) {
        int v = (t >= off) ? s[t - off] : 0;
        __syncthreads();
        s[t] += v;
        __syncthreads();
    }
    if (t < NB) g_bsum[t] = s[t] - x;        // exclusive
}

__global__ void scan3_kernel() {
    int i = blockIdx.x * 256 + threadIdx.x;
    if (i < NN) {
        int v = g_rowptr[i] + g_bsum[i >> 10];
        g_rowptr[i] = v;
        g_cursor[i] = v;
    }
    if (i == 0) g_rowptr[NN] = EE;
}

__global__ void fill_kernel(const int* __restrict__ ei) {
    int e = blockIdx.x * 256 + threadIdx.x;
    if (e < EE) {
        int dst = ei[EE + e];
        int pos = atomicAdd(&g_cursor[dst], 1);
        g_esrc[pos] = ei[e];
    }
}

// ---------------- gather: agg[n] = h[n] + sum_{s in N(n)} h[s] ----------------
// 16 threads per node, one float4 chunk each; 2-edge unroll for MLP
__global__ void gather_kernel() {
    int idx = blockIdx.x * 256 + threadIdx.x;   // grid covers NN*16 exactly
    int n = idx >> 4, c = idx & 15;
    if (n >= NN) return;
    int beg = g_rowptr[n], end = g_rowptr[n + 1];
    const float4* h4 = (const float4*)g_h;
    float4 v = h4[(size_t)n * 16 + c];
    int p = beg;
    for (; p + 2 <= end; p += 2) {
        int s0 = g_esrc[p];
        int s1 = g_esrc[p + 1];
        float4 a0 = h4[(size_t)s0 * 16 + c];
        float4 a1 = h4[(size_t)s1 * 16 + c];
        v.x += a0.x + a1.x;
        v.y += a0.y + a1.y;
        v.z += a0.z + a1.z;
        v.w += a0.w + a1.w;
    }
    if (p < end) {
        int s0 = g_esrc[p];
        float4 a0 = h4[(size_t)s0 * 16 + c];
        v.x += a0.x; v.y += a0.y; v.z += a0.z; v.w += a0.w;
    }
    ((float4*)g_agg)[(size_t)n * 16 + c] = v;
}

// Zs layout: row r at floats [r*64, r*64+64); col k stored at slot
// ((k + 4*(r>>2)) & 63). Rotation multiple of 4 floats keeps float4 alignment;
// the 4 row-groups within a warp land on banks 4 apart -> conflict-free.

// ---------------- GEMM1: z1 = agg @ W1 + b1, plus BN stats ----------------
// 64 rows x 64 cols per block, 128 threads, thread tile = 4 rows x 8 cols
__global__ __launch_bounds__(GT, 6) void gemm1_kernel(const float* __restrict__ W,
                                                      const float* __restrict__ b,
                                                      int layer) {
    extern __shared__ float smp[];
    float* Ws = smp;          // 4096 floats
    float* Zs = smp + 4096;   // 4096 floats
    int t = threadIdx.x;
    int row0 = blockIdx.x * ROWS;

    const float4* Wg = (const float4*)W;
    float4* Ws4 = (float4*)Ws;
#pragma unroll
    for (int i = 0; i < 8; i++) Ws4[t + i * GT] = Wg[t + i * GT];

#pragma unroll
    for (int i = 0; i < 8; i++) {
        int e = t + i * GT;                // 64*16 = 1024 float4s
        int r = e >> 4, c4 = e & 15;
        int gr = row0 + r;
        float4 v = make_float4(0.f, 0.f, 0.f, 0.f);
        if (gr < NN) v = ((const float4*)g_agg)[(size_t)gr * 16 + c4];
        ((float4*)(Zs + r * 64))[(c4 + (r >> 2)) & 15] = v;
    }
    __syncthreads();

    int cw = t & 7;            // col group: cols cw*8 .. cw*8+7
    int g  = t >> 3;           // row group 0..15: rows g*4 .. g*4+3
    int rowb = g * 4;
    u64 acc[4][4];
#pragma unroll
    for (int c = 0; c < 4; c++) {
        u64 bp = pack2(b[cw * 8 + c * 2], b[cw * 8 + c * 2 + 1]);
#pragma unroll
        for (int j = 0; j < 4; j++) acc[j][c] = bp;
    }

    const ulonglong2* Wsu = (const ulonglong2*)Ws;   // 16 units per k-row
#pragma unroll 8
    for (int k = 0; k < 64; k++) {
        ulonglong2 wa = Wsu[k * 16 + cw * 2];
        ulonglong2 wb = Wsu[k * 16 + cw * 2 + 1];
        int kk = (k + 4 * g) & 63;
#pragma unroll
        for (int j = 0; j < 4; j++) {
            float z = Zs[(rowb + j) * 64 + kk];
            u64 zz = pack2(z, z);
            ffma2(acc[j][0], zz, wa.x);
            ffma2(acc[j][1], zz, wa.y);
            ffma2(acc[j][2], zz, wb.x);
            ffma2(acc[j][3], zz, wb.y);
        }
    }
    __syncthreads();   // done reading Zs; reuse it for outputs

#pragma unroll
    for (int j = 0; j < 4; j++) {
        int r = rowb + j;
        int gr = row0 + r;
        float2 p0 = unpack2(acc[j][0]), p1 = unpack2(acc[j][1]);
        float2 p2 = unpack2(acc[j][2]), p3 = unpack2(acc[j][3]);
        float4 o0 = make_float4(p0.x, p0.y, p1.x, p1.y);
        float4 o1 = make_float4(p2.x, p2.y, p3.x, p3.y);
        if (gr < NN) {
            float4* og = (float4*)(g_z1 + (size_t)gr * 64 + cw * 8);
            og[0] = o0; og[1] = o1;
        } else {
            o0 = make_float4(0.f, 0.f, 0.f, 0.f);
            o1 = o0;
        }
        float4* zr = (float4*)(Zs + r * 64);
        zr[(cw * 2 + g) & 15]     = o0;
        zr[(cw * 2 + 1 + g) & 15] = o1;
    }
    __syncthreads();

    // BN stats: 128 threads, 2 row-halves x 64 cols
    {
        int col = t & 63, half = t >> 6;
        float s = 0.f, q = 0.f;
#pragma unroll 8
        for (int r = half * 32; r < half * 32 + 32; r++) {
            float v = Zs[r * 64 + ((col + 4 * (r >> 2)) & 63)];
            s += v;
            q += v * v;
        }
        atomicAdd(&g_bnsum[layer * 64 + col], s);
        atomicAdd(&g_bnsq[layer * 64 + col], q);
    }
}

// ---------------- GEMM2: h = relu(bn(z1)) @ W2 + b2, plus mean-pool ----------------
// BN=false is the embedding GEMM: h = x @ W_emb + b_emb
template <bool BN>
__global__ __launch_bounds__(GT, 6) void gemm2_kernel(const float* __restrict__ in,
                             const float* __restrict__ W, const float* __restrict__ b,
                             const float* __restrict__ gamma, const float* __restrict__ beta,
                             const int* __restrict__ batch, int pool_off, int layer) {
    extern __shared__ float smp[];
    float* Ws = smp;            // 4096
    float* Zs = smp + 4096;     // 4096
    float* sc = smp + 8192;     // 64
    float* sh = smp + 8256;     // 64
    int*   sb = (int*)(smp + 8320);  // 64
    int t = threadIdx.x;
    int row0 = blockIdx.x * ROWS;

    if (t < ROWS) {
        int gr = row0 + t;
        sb[t] = (gr < NN) ? batch[gr] : -1;
    }
    if (t < 64 && BN) {
        float mu = g_bnsum[layer * 64 + t] * (1.f / NN);
        float var = g_bnsq[layer * 64 + t] * (1.f / NN) - mu * mu;
        float rs = rsqrtf(var + 1e-5f);
        float s = gamma[t] * rs;
        sc[t] = s;
        sh[t] = beta[t] - mu * s;
    }
    const float4* Wg = (const float4*)W;
    float4* Ws4 = (float4*)Ws;
#pragma unroll
    for (int i = 0; i < 8; i++) Ws4[t + i * GT] = Wg[t + i * GT];
    __syncthreads();

#pragma unroll
    for (int i = 0; i < 8; i++) {
        int e = t + i * GT;
        int r = e >> 4, c4 = e & 15;
        int gr = row0 + r;
        float4 v = make_float4(0.f, 0.f, 0.f, 0.f);
        if (gr < NN) {
            v = ((const float4*)in)[(size_t)gr * 16 + c4];
            if (BN) {
                int k = c4 * 4;
                v.x = fmaxf(v.x * sc[k]     + sh[k],     0.f);
                v.y = fmaxf(v.y * sc[k + 1] + sh[k + 1], 0.f);
                v.z = fmaxf(v.z * sc[k + 2] + sh[k + 2], 0.f);
                v.w = fmaxf(v.w * sc[k + 3] + sh[k + 3], 0.f);
            }
        }
        ((float4*)(Zs + r * 64))[(c4 + (r >> 2)) & 15] = v;
    }
    __syncthreads();

    int cw = t & 7;
    int g  = t >> 3;
    int rowb = g * 4;
    u64 acc[4][4];
#pragma unroll
    for (int c = 0; c < 4; c++) {
        u64 bp = pack2(b[cw * 8 + c * 2], b[cw * 8 + c * 2 + 1]);
#pragma unroll
        for (int j = 0; j < 4; j++) acc[j][c] = bp;
    }

    const ulonglong2* Wsu = (const ulonglong2*)Ws;
#pragma unroll 8
    for (int k = 0; k < 64; k++) {
        ulonglong2 wa = Wsu[k * 16 + cw * 2];
        ulonglong2 wb = Wsu[k * 16 + cw * 2 + 1];
        int kk = (k + 4 * g) & 63;
#pragma unroll
        for (int j = 0; j < 4; j++) {
            float z = Zs[(rowb + j) * 64 + kk];
            u64 zz = pack2(z, z);
            ffma2(acc[j][0], zz, wa.x);
            ffma2(acc[j][1], zz, wa.y);
            ffma2(acc[j][2], zz, wb.x);
            ffma2(acc[j][3], zz, wb.y);
        }
    }
    __syncthreads();

#pragma unroll
    for (int j = 0; j < 4; j++) {
        int r = rowb + j;
        int gr = row0 + r;
        float2 p0 = unpack2(acc[j][0]), p1 = unpack2(acc[j][1]);
        float2 p2 = unpack2(acc[j][2]), p3 = unpack2(acc[j][3]);
        float4 o0 = make_float4(p0.x, p0.y, p1.x, p1.y);
        float4 o1 = make_float4(p2.x, p2.y, p3.x, p3.y);
        if (gr < NN) {
            float4* og = (float4*)(g_h + (size_t)gr * 64 + cw * 8);
            og[0] = o0; og[1] = o1;
        } else {
            o0 = make_float4(0.f, 0.f, 0.f, 0.f);
            o1 = o0;
        }
        float4* zr = (float4*)(Zs + r * 64);
        zr[(cw * 2 + g) & 15]     = o0;
        zr[(cw * 2 + 1 + g) & 15] = o1;
    }
    __syncthreads();

    // segmented mean-pool accumulation (batch sorted -> few runs per block)
    if (t < 64) {
        float s = 0.f;
        int cur = sb[0];
        for (int r = 0; r < ROWS; r++) {
            int g2 = sb[r];
            if (g2 != cur) {
                if (cur >= 0) atomicAdd(&g_pool[cur * OUTC + pool_off + t], s);
                s = 0.f;
                cur = g2;
            }
            s += Zs[r * 64 + ((t + 4 * (r >> 2)) & 63)];
        }
        if (cur >= 0) atomicAdd(&g_pool[cur * OUTC + pool_off + t], s);
    }
}

__global__ void finalize_kernel(float* __restrict__ out) {
    int i = blockIdx.x * 256 + threadIdx.x;
    if (i < GG * OUTC) {
        int g = i / OUTC;
        float c = (float)max(g_cnt[g], 1);
        out[i] = g_pool[i] / c;
    }
}

// ---------------- host ----------------
extern "C" void kernel_launch(void* const* d_in, const int* in_sizes, int n_in,
                              void* d_out, int out_size) {
    const float* x     = (const float*)d_in[0];
    const int*   ei    = (const int*)d_in[1];
    const int*   batch = (const int*)d_in[2];
    const float* W_emb = (const float*)d_in[3];
    const float* b_emb = (const float*)d_in[4];
    const float* W1    = (const float*)d_in[5];
    const float* b1    = (const float*)d_in[6];
    const float* gamma = (const float*)d_in[7];
    const float* beta  = (const float*)d_in[8];
    const float* W2    = (const float*)d_in[9];
    const float* b2    = (const float*)d_in[10];
    float* out = (float*)d_out;

    cudaFuncSetAttribute(gemm1_kernel, cudaFuncAttributeMaxDynamicSharedMemorySize, SMEM_G);
    cudaFuncSetAttribute(gemm2_kernel<false>, cudaFuncAttributeMaxDynamicSharedMemorySize, SMEM_G);
    cudaFuncSetAttribute(gemm2_kernel<true>, cudaFuncAttributeMaxDynamicSharedMemorySize, SMEM_G);

    void *p_pool, *p_cnt, *p_deg, *p_bnsum, *p_bnsq, *p_z1;
    cudaGetSymbolAddress(&p_pool, g_pool);
    cudaGetSymbolAddress(&p_cnt, g_cnt);
    cudaGetSymbolAddress(&p_deg, g_deg);
    cudaGetSymbolAddress(&p_bnsum, g_bnsum);
    cudaGetSymbolAddress(&p_bnsq, g_bnsq);
    cudaGetSymbolAddress(&p_z1, g_z1);

    cudaMemsetAsync(p_pool, 0, GG * OUTC * sizeof(float), 0);
    cudaMemsetAsync(p_cnt, 0, GG * sizeof(int), 0);
    cudaMemsetAsync(p_deg, 0, NN * sizeof(int), 0);
    cudaMemsetAsync(p_bnsum, 0, 4 * 64 * sizeof(float), 0);
    cudaMemsetAsync(p_bnsq, 0, 4 * 64 * sizeof(float), 0);

    // ---- CSR build (edge structure constant across layers) + graph counts ----
    count_deg_kernel<<<(EE + 255) / 256, 256>>>(batch, ei);
    scan1_kernel<<<NB, 1024>>>();
    scan2_kernel<<<1, 128>>>();
    scan3_kernel<<<(NN + 255) / 256, 256>>>();
    fill_kernel<<<(EE + 255) / 256, 256>>>(ei);

    const int GB = (NN + ROWS - 1) / ROWS;  // 1563 row-tiles

    // embedding GEMM + pool into columns [0,64)
    gemm2_kernel<false><<<GB, GT, SMEM_G>>>(x, W_emb, b_emb, nullptr, nullptr, batch, 0, 0);

    for (int l = 0; l < 4; l++) {
        gather_kernel<<<(NN * 16 + 255) / 256, 256>>>();
        gemm1_kernel<<<GB, GT, SMEM_G>>>(W1 + l * 4096, b1 + l * 64, l);
        gemm2_kernel<true><<<GB, GT, SMEM_G>>>((const float*)p_z1, W2 + l * 4096, b2 + l * 64,
                                        gamma + l * 64, beta + l * 64, batch,
                                        (l + 1) * 64, l);
    }

    finalize_kernel<<<(GG * OUTC + 255) / 256, 256>>>(out);
}

// round 11
// speedup vs baseline: 1.0519x; 1.0048x over previous
#include <cuda_runtime.h>

#define NN 100000
#define EE 1200000
#define GG 128
#define OUTC 320        // 64*(4+1)
#define ROWS 64         // rows per GEMM block
#define GT 128          // threads per GEMM block
#define SMEM_G 33536    // (4096 + 4096 + 64 + 64 + 64) floats * 4
#define NB 98           // scan blocks = ceil(NN/1024)

typedef unsigned long long u64;

// ---------------- scratch (static __device__, no allocation) ----------------
__device__ __align__(128) float g_h[NN * 64];
__device__ __align__(128) float g_agg[NN * 64];
__device__ __align__(128) float g_z1[NN * 64];
__device__ int   g_esrc[EE];
__device__ int   g_rowptr[NN + 1];
__device__ int   g_cursor[NN];
__device__ int   g_deg[NN];
__device__ int   g_bsum[NB];
__device__ float g_pool[GG * OUTC];
__device__ int   g_cnt[GG];
__device__ float g_bnsum[4 * 64];
__device__ float g_bnsq[4 * 64];

// ---------------- packed f32x2 helpers ----------------
__device__ __forceinline__ u64 pack2(float x, float y) {
    u64 r; asm("mov.b64 %0, {%1, %2};" : "=l"(r) : "f"(x), "f"(y)); return r;
}
__device__ __forceinline__ void ffma2(u64& d, u64 a, u64 b) {
    asm("fma.rn.f32x2 %0, %1, %2, %0;" : "+l"(d) : "l"(a), "l"(b));
}
__device__ __forceinline__ float2 unpack2(u64 v) {
    float2 f; asm("mov.b64 {%0, %1}, %2;" : "=f"(f.x), "=f"(f.y) : "l"(v)); return f;
}

// ---------------- fused: per-graph node counts + in-degree histogram ----------
__global__ void count_deg_kernel(const int* __restrict__ batch,
                                 const int* __restrict__ ei) {
    int i = blockIdx.x * 256 + threadIdx.x;
    if (i < NN) atomicAdd(&g_cnt[batch[i]], 1);
    if (i < EE) atomicAdd(&g_deg[ei[EE + i]], 1);
}

// ---------------- CSR build ----------------
__global__ void scan1_kernel() {
    __shared__ int s[1024];
    int t = threadIdx.x;
    int i = blockIdx.x * 1024 + t;
    int x = (i < NN) ? g_deg[i] : 0;
    s[t] = x;
    __syncthreads();
#pragma unroll
    for (int off = 1; off < 1024; off <<= 1) {
        int v = (t >= off) ? s[t - off] : 0;
        __syncthreads();
        s[t] += v;
        __syncthreads();
    }
    if (i < NN) g_rowptr[i] = s[t] - x;      // exclusive, partial
    if (t == 1023) g_bsum[blockIdx.x] = s[1023];
}

// merged scan2+scan3: block b adds prefix sum of bsum[0..b) to its 1024 rows
__global__ void scan23_kernel() {
    __shared__ int sm[128];
    int t = threadIdx.x;
    int b = blockIdx.x;
    if (t < 128) sm[t] = (t < b && t < NB) ? g_bsum[t] : 0;
    __syncthreads();
#pragma unroll
    for (int off = 64; off >= 1; off >>= 1) {
        if (t < off) sm[t] += sm[t + off];
        __syncthreads();
    }
    int prefix = sm[0];
    int i = b * 1024 + t;
    if (i < NN) {
        int v = g_rowptr[i] + prefix;
        g_rowptr[i] = v;
        g_cursor[i] = v;
    }
    if (i == 0) g_rowptr[NN] = EE;
}

__global__ void fill_kernel(const int* __restrict__ ei) {
    int e = blockIdx.x * 256 + threadIdx.x;
    if (e < EE) {
        int dst = ei[EE + e];
        int pos = atomicAdd(&g_cursor[dst], 1);
        g_esrc[pos] = ei[e];
    }
}

// ---------------- gather: agg[n] = h[n] + sum_{s in N(n)} h[s] ----------------
// 16 threads per node, one float4 chunk each; 4-edge unroll for MLP
__global__ void gather_kernel() {
    int idx = blockIdx.x * 256 + threadIdx.x;   // grid covers NN*16 exactly
    int n = idx >> 4, c = idx & 15;
    if (n >= NN) return;
    int beg = g_rowptr[n], end = g_rowptr[n + 1];
    const float4* h4 = (const float4*)g_h;
    float4 v = h4[(size_t)n * 16 + c];
    int p = beg;
    for (; p + 4 <= end; p += 4) {
        int s0 = g_esrc[p];
        int s1 = g_esrc[p + 1];
        int s2 = g_esrc[p + 2];
        int s3 = g_esrc[p + 3];
        float4 a0 = h4[(size_t)s0 * 16 + c];
        float4 a1 = h4[(size_t)s1 * 16 + c];
        float4 a2 = h4[(size_t)s2 * 16 + c];
        float4 a3 = h4[(size_t)s3 * 16 + c];
        v.x += (a0.x + a1.x) + (a2.x + a3.x);
        v.y += (a0.y + a1.y) + (a2.y + a3.y);
        v.z += (a0.z + a1.z) + (a2.z + a3.z);
        v.w += (a0.w + a1.w) + (a2.w + a3.w);
    }
    for (; p < end; p++) {
        int s0 = g_esrc[p];
        float4 a0 = h4[(size_t)s0 * 16 + c];
        v.x += a0.x; v.y += a0.y; v.z += a0.z; v.w += a0.w;
    }
    ((float4*)g_agg)[(size_t)n * 16 + c] = v;
}

// Zs layout: row r at floats [r*64, r*64+64); col k stored at slot
// ((k + 4*(r>>2)) & 63). Rotation multiple of 4 floats keeps float4 alignment;
// the 4 row-groups within a warp land on banks 4 apart -> conflict-free.

// ---------------- GEMM1: z1 = agg @ W1 + b1, plus BN stats ----------------
// 64 rows x 64 cols per block, 128 threads, thread tile = 4 rows x 8 cols
__global__ __launch_bounds__(GT, 6) void gemm1_kernel(const float* __restrict__ W,
                                                      const float* __restrict__ b,
                                                      int layer) {
    extern __shared__ float smp[];
    float* Ws = smp;          // 4096 floats
    float* Zs = smp + 4096;   // 4096 floats
    int t = threadIdx.x;
    int row0 = blockIdx.x * ROWS;

    const float4* Wg = (const float4*)W;
    float4* Ws4 = (float4*)Ws;
#pragma unroll
    for (int i = 0; i < 8; i++) Ws4[t + i * GT] = Wg[t + i * GT];

#pragma unroll
    for (int i = 0; i < 8; i++) {
        int e = t + i * GT;                // 64*16 = 1024 float4s
        int r = e >> 4, c4 = e & 15;
        int gr = row0 + r;
        float4 v = make_float4(0.f, 0.f, 0.f, 0.f);
        if (gr < NN) v = ((const float4*)g_agg)[(size_t)gr * 16 + c4];
        ((float4*)(Zs + r * 64))[(c4 + (r >> 2)) & 15] = v;
    }
    __syncthreads();

    int cw = t & 7;            // col group: cols cw*8 .. cw*8+7
    int g  = t >> 3;           // row group 0..15: rows g*4 .. g*4+3
    int rowb = g * 4;
    u64 acc[4][4];
#pragma unroll
    for (int c = 0; c < 4; c++) {
        u64 bp = pack2(b[cw * 8 + c * 2], b[cw * 8 + c * 2 + 1]);
#pragma unroll
        for (int j = 0; j < 4; j++) acc[j][c] = bp;
    }

    const ulonglong2* Wsu = (const ulonglong2*)Ws;   // 16 units per k-row
#pragma unroll 8
    for (int k = 0; k < 64; k++) {
        ulonglong2 wa = Wsu[k * 16 + cw * 2];
        ulonglong2 wb = Wsu[k * 16 + cw * 2 + 1];
        int kk = (k + 4 * g) & 63;
#pragma unroll
        for (int j = 0; j < 4; j++) {
            float z = Zs[(rowb + j) * 64 + kk];
            u64 zz = pack2(z, z);
            ffma2(acc[j][0], zz, wa.x);
            ffma2(acc[j][1], zz, wa.y);
            ffma2(acc[j][2], zz, wb.x);
            ffma2(acc[j][3], zz, wb.y);
        }
    }
    __syncthreads();   // done reading Zs; reuse it for outputs

#pragma unroll
    for (int j = 0; j < 4; j++) {
        int r = rowb + j;
        int gr = row0 + r;
        float2 p0 = unpack2(acc[j][0]), p1 = unpack2(acc[j][1]);
        float2 p2 = unpack2(acc[j][2]), p3 = unpack2(acc[j][3]);
        float4 o0 = make_float4(p0.x, p0.y, p1.x, p1.y);
        float4 o1 = make_float4(p2.x, p2.y, p3.x, p3.y);
        if (gr < NN) {
            float4* og = (float4*)(g_z1 + (size_t)gr * 64 + cw * 8);
            og[0] = o0; og[1] = o1;
        } else {
            o0 = make_float4(0.f, 0.f, 0.f, 0.f);
            o1 = o0;
        }
        float4* zr = (float4*)(Zs + r * 64);
        zr[(cw * 2 + g) & 15]     = o0;
        zr[(cw * 2 + 1 + g) & 15] = o1;
    }
    __syncthreads();

    // BN stats: 128 threads, 2 row-halves x 64 cols
    {
        int col = t & 63, half = t >> 6;
        float s = 0.f, q = 0.f;
#pragma unroll 8
        for (int r = half * 32; r < half * 32 + 32; r++) {
            float v = Zs[r * 64 + ((col + 4 * (r >> 2)) & 63)];
            s += v;
            q += v * v;
        }
        atomicAdd(&g_bnsum[layer * 64 + col], s);
        atomicAdd(&g_bnsq[layer * 64 + col], q);
    }
}

// ---------------- GEMM2: h = relu(bn(z1)) @ W2 + b2, plus mean-pool ----------------
// BN=false is the embedding GEMM: h = x @ W_emb + b_emb
template <bool BN>
__global__ __launch_bounds__(GT, 6) void gemm2_kernel(const float* __restrict__ in,
                             const float* __restrict__ W, const float* __restrict__ b,
                             const float* __restrict__ gamma, const float* __restrict__ beta,
                             const int* __restrict__ batch, int pool_off, int layer) {
    extern __shared__ float smp[];
    float* Ws = smp;            // 4096
    float* Zs = smp + 4096;     // 4096
    float* sc = smp + 8192;     // 64
    float* sh = smp + 8256;     // 64
    int*   sb = (int*)(smp + 8320);  // 64
    int t = threadIdx.x;
    int row0 = blockIdx.x * ROWS;

    if (t < ROWS) {
        int gr = row0 + t;
        sb[t] = (gr < NN) ? batch[gr] : -1;
    }
    if (t < 64 && BN) {
        float mu = g_bnsum[layer * 64 + t] * (1.f / NN);
        float var = g_bnsq[layer * 64 + t] * (1.f / NN) - mu * mu;
        float rs = rsqrtf(var + 1e-5f);
        float s = gamma[t] * rs;
        sc[t] = s;
        sh[t] = beta[t] - mu * s;
    }
    const float4* Wg = (const float4*)W;
    float4* Ws4 = (float4*)Ws;
#pragma unroll
    for (int i = 0; i < 8; i++) Ws4[t + i * GT] = Wg[t + i * GT];
    __syncthreads();

#pragma unroll
    for (int i = 0; i < 8; i++) {
        int e = t + i * GT;
        int r = e >> 4, c4 = e & 15;
        int gr = row0 + r;
        float4 v = make_float4(0.f, 0.f, 0.f, 0.f);
        if (gr < NN) {
            v = ((const float4*)in)[(size_t)gr * 16 + c4];
            if (BN) {
                int k = c4 * 4;
                v.x = fmaxf(v.x * sc[k]     + sh[k],     0.f);
                v.y = fmaxf(v.y * sc[k + 1] + sh[k + 1], 0.f);
                v.z = fmaxf(v.z * sc[k + 2] + sh[k + 2], 0.f);
                v.w = fmaxf(v.w * sc[k + 3] + sh[k + 3], 0.f);
            }
        }
        ((float4*)(Zs + r * 64))[(c4 + (r >> 2)) & 15] = v;
    }
    __syncthreads();

    int cw = t & 7;
    int g  = t >> 3;
    int rowb = g * 4;
    u64 acc[4][4];
#pragma unroll
    for (int c = 0; c < 4; c++) {
        u64 bp = pack2(b[cw * 8 + c * 2], b[cw * 8 + c * 2 + 1]);
#pragma unroll
        for (int j = 0; j < 4; j++) acc[j][c] = bp;
    }

    const ulonglong2* Wsu = (const ulonglong2*)Ws;
#pragma unroll 8
    for (int k = 0; k < 64; k++) {
        ulonglong2 wa = Wsu[k * 16 + cw * 2];
        ulonglong2 wb = Wsu[k * 16 + cw * 2 + 1];
        int kk = (k + 4 * g) & 63;
#pragma unroll
        for (int j = 0; j < 4; j++) {
            float z = Zs[(rowb + j) * 64 + kk];
            u64 zz = pack2(z, z);
            ffma2(acc[j][0], zz, wa.x);
            ffma2(acc[j][1], zz, wa.y);
            ffma2(acc[j][2], zz, wb.x);
            ffma2(acc[j][3], zz, wb.y);
        }
    }
    __syncthreads();

#pragma unroll
    for (int j = 0; j < 4; j++) {
        int r = rowb + j;
        int gr = row0 + r;
        float2 p0 = unpack2(acc[j][0]), p1 = unpack2(acc[j][1]);
        float2 p2 = unpack2(acc[j][2]), p3 = unpack2(acc[j][3]);
        float4 o0 = make_float4(p0.x, p0.y, p1.x, p1.y);
        float4 o1 = make_float4(p2.x, p2.y, p3.x, p3.y);
        if (gr < NN) {
            float4* og = (float4*)(g_h + (size_t)gr * 64 + cw * 8);
            og[0] = o0; og[1] = o1;
        } else {
            o0 = make_float4(0.f, 0.f, 0.f, 0.f);
            o1 = o0;
        }
        float4* zr = (float4*)(Zs + r * 64);
        zr[(cw * 2 + g) & 15]     = o0;
        zr[(cw * 2 + 1 + g) & 15] = o1;
    }
    __syncthreads();

    // segmented mean-pool accumulation (batch sorted -> few runs per block)
    if (t < 64) {
        float s = 0.f;
        int cur = sb[0];
        for (int r = 0; r < ROWS; r++) {
            int g2 = sb[r];
            if (g2 != cur) {
                if (cur >= 0) atomicAdd(&g_pool[cur * OUTC + pool_off + t], s);
                s = 0.f;
                cur = g2;
            }
            s += Zs[r * 64 + ((t + 4 * (r >> 2)) & 63)];
        }
        if (cur >= 0) atomicAdd(&g_pool[cur * OUTC + pool_off + t], s);
    }
}

__global__ void finalize_kernel(float* __restrict__ out) {
    int i = blockIdx.x * 256 + threadIdx.x;
    if (i < GG * OUTC) {
        int g = i / OUTC;
        float c = (float)max(g_cnt[g], 1);
        out[i] = g_pool[i] / c;
    }
}

// ---------------- host ----------------
extern "C" void kernel_launch(void* const* d_in, const int* in_sizes, int n_in,
                              void* d_out, int out_size) {
    const float* x     = (const float*)d_in[0];
    const int*   ei    = (const int*)d_in[1];
    const int*   batch = (const int*)d_in[2];
    const float* W_emb = (const float*)d_in[3];
    const float* b_emb = (const float*)d_in[4];
    const float* W1    = (const float*)d_in[5];
    const float* b1    = (const float*)d_in[6];
    const float* gamma = (const float*)d_in[7];
    const float* beta  = (const float*)d_in[8];
    const float* W2    = (const float*)d_in[9];
    const float* b2    = (const float*)d_in[10];
    float* out = (float*)d_out;

    // persistent side-stream + events (host resources only; created once,
    // identical device work recorded on every call)
    static cudaStream_t sB = nullptr;
    static cudaEvent_t evFork = nullptr, evJoin = nullptr;
    if (sB == nullptr) {
        cudaStreamCreateWithFlags(&sB, cudaStreamNonBlocking);
        cudaEventCreateWithFlags(&evFork, cudaEventDisableTiming);
        cudaEventCreateWithFlags(&evJoin, cudaEventDisableTiming);
    }

    cudaFuncSetAttribute(gemm1_kernel, cudaFuncAttributeMaxDynamicSharedMemorySize, SMEM_G);
    cudaFuncSetAttribute(gemm2_kernel<false>, cudaFuncAttributeMaxDynamicSharedMemorySize, SMEM_G);
    cudaFuncSetAttribute(gemm2_kernel<true>, cudaFuncAttributeMaxDynamicSharedMemorySize, SMEM_G);

    void *p_pool, *p_cnt, *p_deg, *p_bnsum, *p_bnsq, *p_z1;
    cudaGetSymbolAddress(&p_pool, g_pool);
    cudaGetSymbolAddress(&p_cnt, g_cnt);
    cudaGetSymbolAddress(&p_deg, g_deg);
    cudaGetSymbolAddress(&p_bnsum, g_bnsum);
    cudaGetSymbolAddress(&p_bnsq, g_bnsq);
    cudaGetSymbolAddress(&p_z1, g_z1);

    cudaMemsetAsync(p_pool, 0, GG * OUTC * sizeof(float), 0);
    cudaMemsetAsync(p_cnt, 0, GG * sizeof(int), 0);
    cudaMemsetAsync(p_deg, 0, NN * sizeof(int), 0);
    cudaMemsetAsync(p_bnsum, 0, 4 * 64 * sizeof(float), 0);
    cudaMemsetAsync(p_bnsq, 0, 4 * 64 * sizeof(float), 0);

    const int GB = (NN + ROWS - 1) / ROWS;  // 1563 row-tiles

    // fork: embedding GEMM (independent of CSR build) on side stream
    cudaEventRecord(evFork, 0);
    cudaStreamWaitEvent(sB, evFork, 0);
    gemm2_kernel<false><<<GB, GT, SMEM_G, sB>>>(x, W_emb, b_emb, nullptr, nullptr,
                                                batch, 0, 0);
    cudaEventRecord(evJoin, sB);

    // CSR build on the main stream, concurrent with the embedding GEMM
    count_deg_kernel<<<(EE + 255) / 256, 256>>>(batch, ei);
    scan1_kernel<<<NB, 1024>>>();
    scan23_kernel<<<NB, 1024>>>();
    fill_kernel<<<(EE + 255) / 256, 256>>>(ei);

    // join: layer loop needs both g_h (embedding) and g_esrc (CSR)
    cudaStreamWaitEvent(0, evJoin, 0);

    for (int l = 0; l < 4; l++) {
        gather_kernel<<<(NN * 16 + 255) / 256, 256>>>();
        gemm1_kernel<<<GB, GT, SMEM_G>>>(W1 + l * 4096, b1 + l * 64, l);
        gemm2_kernel<true><<<GB, GT, SMEM_G>>>((const float*)p_z1, W2 + l * 4096, b2 + l * 64,
                                        gamma + l * 64, beta + l * 64, batch,
                                        (l + 1) * 64, l);
    }

    finalize_kernel<<<(GG * OUTC + 255) / 256, 256>>>(out);
}

// round 12
// speedup vs baseline: 1.0542x; 1.0022x over previous
#include <cuda_runtime.h>

#define NN 100000
#define EE 1200000
#define GG 128
#define OUTC 320        // 64*(4+1)
#define ROWS 64         // rows per GEMM tile
#define GT 128          // threads per GEMM block
#define TPB 2           // tiles per persistent GEMM block
#define GBP 782         // GEMM grid: 782*2 = 1564 tiles >= 1563
#define SMEM_G 33536    // (4096 + 4096 + 64 + 64 + 64) floats * 4
#define NB 98           // scan blocks = ceil(NN/1024)

typedef unsigned long long u64;

// ---------------- scratch (static __device__, no allocation) ----------------
__device__ __align__(128) float g_h[NN * 64];
__device__ __align__(128) float g_agg[NN * 64];
__device__ __align__(128) float g_z1[NN * 64];
__device__ int   g_esrc[EE];
__device__ int   g_rowptr[NN + 1];
__device__ int   g_cursor[NN];
__device__ int   g_deg[NN];
__device__ int   g_bsum[NB];
__device__ float g_pool[GG * OUTC];
__device__ int   g_cnt[GG];
__device__ float g_bnsum[4 * 64];
__device__ float g_bnsq[4 * 64];

// ---------------- packed f32x2 helpers ----------------
__device__ __forceinline__ u64 pack2(float x, float y) {
    u64 r; asm("mov.b64 %0, {%1, %2};" : "=l"(r) : "f"(x), "f"(y)); return r;
}
__device__ __forceinline__ void ffma2(u64& d, u64 a, u64 b) {
    asm("fma.rn.f32x2 %0, %1, %2, %0;" : "+l"(d) : "l"(a), "l"(b));
}
__device__ __forceinline__ float2 unpack2(u64 v) {
    float2 f; asm("mov.b64 {%0, %1}, %2;" : "=f"(f.x), "=f"(f.y) : "l"(v)); return f;
}

// ---------------- one kernel clears all small scratch ----------------
__global__ void clear_kernel() {
    int i = blockIdx.x * 256 + threadIdx.x;
    if (i < GG * OUTC) g_pool[i] = 0.f;
    if (i < GG) g_cnt[i] = 0;
    if (i < NN) g_deg[i] = 0;
    if (i < 4 * 64) { g_bnsum[i] = 0.f; g_bnsq[i] = 0.f; }
}

// ---------------- fused: per-graph node counts + in-degree histogram ----------
__global__ void count_deg_kernel(const int* __restrict__ batch,
                                 const int* __restrict__ ei) {
    int i = blockIdx.x * 256 + threadIdx.x;
    if (i < NN) atomicAdd(&g_cnt[batch[i]], 1);
    if (i < EE) atomicAdd(&g_deg[ei[EE + i]], 1);
}

// ---------------- CSR build ----------------
__global__ void scan1_kernel() {
    __shared__ int s[1024];
    int t = threadIdx.x;
    int i = blockIdx.x * 1024 + t;
    int x = (i < NN) ? g_deg[i] : 0;
    s[t] = x;
    __syncthreads();
#pragma unroll
    for (int off = 1; off < 1024; off <<= 1) {
        int v = (t >= off) ? s[t - off] : 0;
        __syncthreads();
        s[t] += v;
        __syncthreads();
    }
    if (i < NN) g_rowptr[i] = s[t] - x;      // exclusive, partial
    if (t == 1023) g_bsum[blockIdx.x] = s[1023];
}

// merged scan2+scan3: block b adds prefix sum of bsum[0..b) to its 1024 rows
__global__ void scan23_kernel() {
    __shared__ int sm[128];
    int t = threadIdx.x;
    int b = blockIdx.x;
    if (t < 128) sm[t] = (t < b && t < NB) ? g_bsum[t] : 0;
    __syncthreads();
#pragma unroll
    for (int off = 64; off >= 1; off >>= 1) {
        if (t < off) sm[t] += sm[t + off];
        __syncthreads();
    }
    int prefix = sm[0];
    int i = b * 1024 + t;
    if (i < NN) {
        int v = g_rowptr[i] + prefix;
        g_rowptr[i] = v;
        g_cursor[i] = v;
    }
    if (i == 0) g_rowptr[NN] = EE;
}

__global__ void fill_kernel(const int* __restrict__ ei) {
    int e = blockIdx.x * 256 + threadIdx.x;
    if (e < EE) {
        int dst = ei[EE + e];
        int pos = atomicAdd(&g_cursor[dst], 1);
        g_esrc[pos] = ei[e];
    }
}

// ---------------- gather: agg[n] = h[n] + sum_{s in N(n)} h[s] ----------------
// 16 threads per node, one float4 chunk each; 4-edge unroll for MLP
__global__ void gather_kernel() {
    int idx = blockIdx.x * 256 + threadIdx.x;   // grid covers NN*16 exactly
    int n = idx >> 4, c = idx & 15;
    if (n >= NN) return;
    int beg = g_rowptr[n], end = g_rowptr[n + 1];
    const float4* h4 = (const float4*)g_h;
    float4 v = h4[(size_t)n * 16 + c];
    int p = beg;
    for (; p + 4 <= end; p += 4) {
        int s0 = g_esrc[p];
        int s1 = g_esrc[p + 1];
        int s2 = g_esrc[p + 2];
        int s3 = g_esrc[p + 3];
        float4 a0 = h4[(size_t)s0 * 16 + c];
        float4 a1 = h4[(size_t)s1 * 16 + c];
        float4 a2 = h4[(size_t)s2 * 16 + c];
        float4 a3 = h4[(size_t)s3 * 16 + c];
        v.x += (a0.x + a1.x) + (a2.x + a3.x);
        v.y += (a0.y + a1.y) + (a2.y + a3.y);
        v.z += (a0.z + a1.z) + (a2.z + a3.z);
        v.w += (a0.w + a1.w) + (a2.w + a3.w);
    }
    for (; p < end; p++) {
        int s0 = g_esrc[p];
        float4 a0 = h4[(size_t)s0 * 16 + c];
        v.x += a0.x; v.y += a0.y; v.z += a0.z; v.w += a0.w;
    }
    ((float4*)g_agg)[(size_t)n * 16 + c] = v;
}

// Zs layout: row r at floats [r*64, r*64+64); col k stored at slot
// ((k + 4*(r>>2)) & 63). Rotation multiple of 4 floats keeps float4 alignment;
// the 4 row-groups within a warp land on banks 4 apart -> conflict-free.

// ---------------- GEMM1 (persistent, 2 tiles/block): z1 = agg @ W1 + b1 + BN stats
__global__ __launch_bounds__(GT, 6) void gemm1_kernel(const float* __restrict__ W,
                                                      const float* __restrict__ b,
                                                      int layer) {
    extern __shared__ float smp[];
    float* Ws = smp;          // 4096 floats
    float* Zs = smp + 4096;   // 4096 floats
    int t = threadIdx.x;

    const float4* Wg = (const float4*)W;
    float4* Ws4 = (float4*)Ws;
#pragma unroll
    for (int i = 0; i < 8; i++) Ws4[t + i * GT] = Wg[t + i * GT];

    int cw = t & 7;            // col group: cols cw*8 .. cw*8+7
    int g  = t >> 3;           // row group 0..15: rows g*4 .. g*4+3
    int rowb = g * 4;
    u64 bp[4];
#pragma unroll
    for (int c = 0; c < 4; c++) bp[c] = pack2(b[cw * 8 + c * 2], b[cw * 8 + c * 2 + 1]);

    int colS = t & 63, half = t >> 6;
    float ssum = 0.f, sq = 0.f;   // BN partials across tiles

    for (int tile = 0; tile < TPB; tile++) {
        int row0 = (blockIdx.x * TPB + tile) * ROWS;
        // barrier: first iter covers Ws stores; later iters cover stats reads
        __syncthreads();
#pragma unroll
        for (int i = 0; i < 8; i++) {
            int e = t + i * GT;                // 64*16 = 1024 float4s
            int r = e >> 4, c4 = e & 15;
            int gr = row0 + r;
            float4 v = make_float4(0.f, 0.f, 0.f, 0.f);
            if (gr < NN) v = ((const float4*)g_agg)[(size_t)gr * 16 + c4];
            ((float4*)(Zs + r * 64))[(c4 + (r >> 2)) & 15] = v;
        }
        __syncthreads();

        u64 acc[4][4];
#pragma unroll
        for (int c = 0; c < 4; c++)
#pragma unroll
            for (int j = 0; j < 4; j++) acc[j][c] = bp[c];

        const ulonglong2* Wsu = (const ulonglong2*)Ws;   // 16 units per k-row
#pragma unroll 8
        for (int k = 0; k < 64; k++) {
            ulonglong2 wa = Wsu[k * 16 + cw * 2];
            ulonglong2 wb = Wsu[k * 16 + cw * 2 + 1];
            int kk = (k + 4 * g) & 63;
#pragma unroll
            for (int j = 0; j < 4; j++) {
                float z = Zs[(rowb + j) * 64 + kk];
                u64 zz = pack2(z, z);
                ffma2(acc[j][0], zz, wa.x);
                ffma2(acc[j][1], zz, wa.y);
                ffma2(acc[j][2], zz, wb.x);
                ffma2(acc[j][3], zz, wb.y);
            }
        }
        __syncthreads();   // done reading Zs; reuse it for outputs

#pragma unroll
        for (int j = 0; j < 4; j++) {
            int r = rowb + j;
            int gr = row0 + r;
            float2 p0 = unpack2(acc[j][0]), p1 = unpack2(acc[j][1]);
            float2 p2 = unpack2(acc[j][2]), p3 = unpack2(acc[j][3]);
            float4 o0 = make_float4(p0.x, p0.y, p1.x, p1.y);
            float4 o1 = make_float4(p2.x, p2.y, p3.x, p3.y);
            if (gr < NN) {
                float4* og = (float4*)(g_z1 + (size_t)gr * 64 + cw * 8);
                og[0] = o0; og[1] = o1;
            } else {
                o0 = make_float4(0.f, 0.f, 0.f, 0.f);
                o1 = o0;
            }
            float4* zr = (float4*)(Zs + r * 64);
            zr[(cw * 2 + g) & 15]     = o0;
            zr[(cw * 2 + 1 + g) & 15] = o1;
        }
        __syncthreads();

        // BN partials: 128 threads, 2 row-halves x 64 cols
#pragma unroll 8
        for (int r = half * 32; r < half * 32 + 32; r++) {
            float v = Zs[r * 64 + ((colS + 4 * (r >> 2)) & 63)];
            ssum += v;
            sq += v * v;
        }
    }
    atomicAdd(&g_bnsum[layer * 64 + colS], ssum);
    atomicAdd(&g_bnsq[layer * 64 + colS], sq);
}

// ---------------- GEMM2 (persistent, 2 tiles/block): h = relu(bn(z1)) @ W2 + b2 + pool
// BN=false is the embedding GEMM: h = x @ W_emb + b_emb
template <bool BN>
__global__ __launch_bounds__(GT, 6) void gemm2_kernel(const float* __restrict__ in,
                             const float* __restrict__ W, const float* __restrict__ b,
                             const float* __restrict__ gamma, const float* __restrict__ beta,
                             const int* __restrict__ batch, int pool_off, int layer) {
    extern __shared__ float smp[];
    float* Ws = smp;            // 4096
    float* Zs = smp + 4096;     // 4096
    float* sc = smp + 8192;     // 64
    float* sh = smp + 8256;     // 64
    int*   sb = (int*)(smp + 8320);  // 64
    int t = threadIdx.x;

    if (t < 64 && BN) {
        float mu = g_bnsum[layer * 64 + t] * (1.f / NN);
        float var = g_bnsq[layer * 64 + t] * (1.f / NN) - mu * mu;
        float rs = rsqrtf(var + 1e-5f);
        float s = gamma[t] * rs;
        sc[t] = s;
        sh[t] = beta[t] - mu * s;
    }
    const float4* Wg = (const float4*)W;
    float4* Ws4 = (float4*)Ws;
#pragma unroll
    for (int i = 0; i < 8; i++) Ws4[t + i * GT] = Wg[t + i * GT];

    int cw = t & 7;
    int g  = t >> 3;
    int rowb = g * 4;
    u64 bp[4];
#pragma unroll
    for (int c = 0; c < 4; c++) bp[c] = pack2(b[cw * 8 + c * 2], b[cw * 8 + c * 2 + 1]);

    for (int tile = 0; tile < TPB; tile++) {
        int row0 = (blockIdx.x * TPB + tile) * ROWS;
        __syncthreads();   // covers Ws/sc/sh (iter 0) and prior pool reads (iter>0)
        if (t < ROWS) {
            int gr = row0 + t;
            sb[t] = (gr < NN) ? batch[gr] : -1;
        }
#pragma unroll
        for (int i = 0; i < 8; i++) {
            int e = t + i * GT;
            int r = e >> 4, c4 = e & 15;
            int gr = row0 + r;
            float4 v = make_float4(0.f, 0.f, 0.f, 0.f);
            if (gr < NN) {
                v = ((const float4*)in)[(size_t)gr * 16 + c4];
                if (BN) {
                    int k = c4 * 4;
                    v.x = fmaxf(v.x * sc[k]     + sh[k],     0.f);
                    v.y = fmaxf(v.y * sc[k + 1] + sh[k + 1], 0.f);
                    v.z = fmaxf(v.z * sc[k + 2] + sh[k + 2], 0.f);
                    v.w = fmaxf(v.w * sc[k + 3] + sh[k + 3], 0.f);
                }
            }
            ((float4*)(Zs + r * 64))[(c4 + (r >> 2)) & 15] = v;
        }
        __syncthreads();

        u64 acc[4][4];
#pragma unroll
        for (int c = 0; c < 4; c++)
#pragma unroll
            for (int j = 0; j < 4; j++) acc[j][c] = bp[c];

        const ulonglong2* Wsu = (const ulonglong2*)Ws;
#pragma unroll 8
        for (int k = 0; k < 64; k++) {
            ulonglong2 wa = Wsu[k * 16 + cw * 2];
            ulonglong2 wb = Wsu[k * 16 + cw * 2 + 1];
            int kk = (k + 4 * g) & 63;
#pragma unroll
            for (int j = 0; j < 4; j++) {
                float z = Zs[(rowb + j) * 64 + kk];
                u64 zz = pack2(z, z);
                ffma2(acc[j][0], zz, wa.x);
                ffma2(acc[j][1], zz, wa.y);
                ffma2(acc[j][2], zz, wb.x);
                ffma2(acc[j][3], zz, wb.y);
            }
        }
        __syncthreads();

#pragma unroll
        for (int j = 0; j < 4; j++) {
            int r = rowb + j;
            int gr = row0 + r;
            float2 p0 = unpack2(acc[j][0]), p1 = unpack2(acc[j][1]);
            float2 p2 = unpack2(acc[j][2]), p3 = unpack2(acc[j][3]);
            float4 o0 = make_float4(p0.x, p0.y, p1.x, p1.y);
            float4 o1 = make_float4(p2.x, p2.y, p3.x, p3.y);
            if (gr < NN) {
                float4* og = (float4*)(g_h + (size_t)gr * 64 + cw * 8);
                og[0] = o0; og[1] = o1;
            } else {
                o0 = make_float4(0.f, 0.f, 0.f, 0.f);
                o1 = o0;
            }
            float4* zr = (float4*)(Zs + r * 64);
            zr[(cw * 2 + g) & 15]     = o0;
            zr[(cw * 2 + 1 + g) & 15] = o1;
        }
        __syncthreads();

        // segmented mean-pool accumulation (batch sorted -> few runs per block)
        if (t < 64) {
            float s = 0.f;
            int cur = sb[0];
            for (int r = 0; r < ROWS; r++) {
                int g2 = sb[r];
                if (g2 != cur) {
                    if (cur >= 0) atomicAdd(&g_pool[cur * OUTC + pool_off + t], s);
                    s = 0.f;
                    cur = g2;
                }
                s += Zs[r * 64 + ((t + 4 * (r >> 2)) & 63)];
            }
            if (cur >= 0) atomicAdd(&g_pool[cur * OUTC + pool_off + t], s);
        }
    }
}

__global__ void finalize_kernel(float* __restrict__ out) {
    int i = blockIdx.x * 256 + threadIdx.x;
    if (i < GG * OUTC) {
        int g = i / OUTC;
        float c = (float)max(g_cnt[g], 1);
        out[i] = g_pool[i] / c;
    }
}

// ---------------- host ----------------
extern "C" void kernel_launch(void* const* d_in, const int* in_sizes, int n_in,
                              void* d_out, int out_size) {
    const float* x     = (const float*)d_in[0];
    const int*   ei    = (const int*)d_in[1];
    const int*   batch = (const int*)d_in[2];
    const float* W_emb = (const float*)d_in[3];
    const float* b_emb = (const float*)d_in[4];
    const float* W1    = (const float*)d_in[5];
    const float* b1    = (const float*)d_in[6];
    const float* gamma = (const float*)d_in[7];
    const float* beta  = (const float*)d_in[8];
    const float* W2    = (const float*)d_in[9];
    const float* b2    = (const float*)d_in[10];
    float* out = (float*)d_out;

    // persistent side-stream + events (host resources only; created once)
    static cudaStream_t sB = nullptr;
    static cudaEvent_t evFork = nullptr, evJoin = nullptr;
    if (sB == nullptr) {
        cudaStreamCreateWithFlags(&sB, cudaStreamNonBlocking);
        cudaEventCreateWithFlags(&evFork, cudaEventDisableTiming);
        cudaEventCreateWithFlags(&evJoin, cudaEventDisableTiming);
    }

    cudaFuncSetAttribute(gemm1_kernel, cudaFuncAttributeMaxDynamicSharedMemorySize, SMEM_G);
    cudaFuncSetAttribute(gemm2_kernel<false>, cudaFuncAttributeMaxDynamicSharedMemorySize, SMEM_G);
    cudaFuncSetAttribute(gemm2_kernel<true>, cudaFuncAttributeMaxDynamicSharedMemorySize, SMEM_G);

    void* p_z1;
    cudaGetSymbolAddress(&p_z1, g_z1);

    clear_kernel<<<(NN + 255) / 256, 256>>>();

    // fork: embedding GEMM (independent of CSR build) on side stream
    cudaEventRecord(evFork, 0);
    cudaStreamWaitEvent(sB, evFork, 0);
    gemm2_kernel<false><<<GBP, GT, SMEM_G, sB>>>(x, W_emb, b_emb, nullptr, nullptr,
                                                 batch, 0, 0);
    cudaEventRecord(evJoin, sB);

    // CSR build on the main stream, concurrent with the embedding GEMM
    count_deg_kernel<<<(EE + 255) / 256, 256>>>(batch, ei);
    scan1_kernel<<<NB, 1024>>>();
    scan23_kernel<<<NB, 1024>>>();
    fill_kernel<<<(EE + 255) / 256, 256>>>(ei);

    // join: layer loop needs both g_h (embedding) and g_esrc (CSR)
    cudaStreamWaitEvent(0, evJoin, 0);

    for (int l = 0; l < 4; l++) {
        gather_kernel<<<(NN * 16 + 255) / 256, 256>>>();
        gemm1_kernel<<<GBP, GT, SMEM_G>>>(W1 + l * 4096, b1 + l * 64, l);
        gemm2_kernel<true><<<GBP, GT, SMEM_G>>>((const float*)p_z1, W2 + l * 4096, b2 + l * 64,
                                        gamma + l * 64, beta + l * 64, batch,
                                        (l + 1) * 64, l);
    }

    finalize_kernel<<<(GG * OUTC + 255) / 256, 256>>>(out);
}

// round 13
// speedup vs baseline: 1.1541x; 1.0948x over previous
#include <cuda_runtime.h>
#include <cuda_bf16.h>

#define NN 100000
#define EE 1200000
#define GG 128
#define OUTC 320        // 64*(4+1)
#define ROWS 64         // rows per GEMM tile
#define GT 128          // threads per GEMM block
#define TPB 2           // tiles per persistent GEMM block
#define GBP 782         // GEMM grid: 782*2 = 1564 tiles >= 1563
#define SMEM_G 33536    // (4096 + 4096 + 64 + 64 + 64) floats * 4
#define NB 98           // scan blocks = ceil(NN/1024)

typedef unsigned long long u64;
typedef unsigned int u32;

// ---------------- scratch (static __device__, no allocation) ----------------
__device__ __align__(128) float g_h[NN * 64];
__device__ __align__(128) __nv_bfloat16 g_hb[NN * 64];   // bf16 mirror of h
__device__ __align__(128) float g_agg[NN * 64];
__device__ __align__(128) float g_z1[NN * 64];
__device__ int   g_esrc[EE];
__device__ int   g_rowptr[NN + 1];
__device__ int   g_cursor[NN];
__device__ int   g_deg[NN];
__device__ int   g_bsum[NB];
__device__ float g_pool[GG * OUTC];
__device__ int   g_cnt[GG];
__device__ float g_bnsum[4 * 64];
__device__ float g_bnsq[4 * 64];

// ---------------- packed f32x2 helpers ----------------
__device__ __forceinline__ u64 pack2(float x, float y) {
    u64 r; asm("mov.b64 %0, {%1, %2};" : "=l"(r) : "f"(x), "f"(y)); return r;
}
__device__ __forceinline__ void ffma2(u64& d, u64 a, u64 b) {
    asm("fma.rn.f32x2 %0, %1, %2, %0;" : "+l"(d) : "l"(a), "l"(b));
}
__device__ __forceinline__ float2 unpack2(u64 v) {
    float2 f; asm("mov.b64 {%0, %1}, %2;" : "=f"(f.x), "=f"(f.y) : "l"(v)); return f;
}

// ---------------- one kernel clears all small scratch ----------------
__global__ void clear_kernel() {
    int i = blockIdx.x * 256 + threadIdx.x;
    if (i < GG * OUTC) g_pool[i] = 0.f;
    if (i < GG) g_cnt[i] = 0;
    if (i < NN) g_deg[i] = 0;
    if (i < 4 * 64) { g_bnsum[i] = 0.f; g_bnsq[i] = 0.f; }
}

// ---------------- fused: per-graph node counts + in-degree histogram ----------
__global__ void count_deg_kernel(const int* __restrict__ batch,
                                 const int* __restrict__ ei) {
    int i = blockIdx.x * 256 + threadIdx.x;
    if (i < NN) atomicAdd(&g_cnt[batch[i]], 1);
    if (i < EE) atomicAdd(&g_deg[ei[EE + i]], 1);
}

// ---------------- CSR build ----------------
__global__ void scan1_kernel() {
    __shared__ int s[1024];
    int t = threadIdx.x;
    int i = blockIdx.x * 1024 + t;
    int x = (i < NN) ? g_deg[i] : 0;
    s[t] = x;
    __syncthreads();
#pragma unroll
    for (int off = 1; off < 1024; off <<= 1) {
        int v = (t >= off) ? s[t - off] : 0;
        __syncthreads();
        s[t] += v;
        __syncthreads();
    }
    if (i < NN) g_rowptr[i] = s[t] - x;      // exclusive, partial
    if (t == 1023) g_bsum[blockIdx.x] = s[1023];
}

// merged scan2+scan3: block b adds prefix sum of bsum[0..b) to its 1024 rows
__global__ void scan23_kernel() {
    __shared__ int sm[128];
    int t = threadIdx.x;
    int b = blockIdx.x;
    if (t < 128) sm[t] = (t < b && t < NB) ? g_bsum[t] : 0;
    __syncthreads();
#pragma unroll
    for (int off = 64; off >= 1; off >>= 1) {
        if (t < off) sm[t] += sm[t + off];
        __syncthreads();
    }
    int prefix = sm[0];
    int i = b * 1024 + t;
    if (i < NN) {
        int v = g_rowptr[i] + prefix;
        g_rowptr[i] = v;
        g_cursor[i] = v;
    }
    if (i == 0) g_rowptr[NN] = EE;
}

__global__ void fill_kernel(const int* __restrict__ ei) {
    int e = blockIdx.x * 256 + threadIdx.x;
    if (e < EE) {
        int dst = ei[EE + e];
        int pos = atomicAdd(&g_cursor[dst], 1);
        g_esrc[pos] = ei[e];
    }
}

// ---------------- gather: agg[n] = h[n] + sum_{s in N(n)} hb[s] (bf16) -------
// 8 threads per node, 8 columns (16B bf16) each; 4-edge unroll for MLP
__device__ __forceinline__ void acc8(float4& v0, float4& v1, uint4 a) {
    v0.x += __uint_as_float(a.x << 16);
    v0.y += __uint_as_float(a.x & 0xFFFF0000u);
    v0.z += __uint_as_float(a.y << 16);
    v0.w += __uint_as_float(a.y & 0xFFFF0000u);
    v1.x += __uint_as_float(a.z << 16);
    v1.y += __uint_as_float(a.z & 0xFFFF0000u);
    v1.z += __uint_as_float(a.w << 16);
    v1.w += __uint_as_float(a.w & 0xFFFF0000u);
}

__global__ void gather_kernel() {
    int idx = blockIdx.x * 256 + threadIdx.x;   // grid covers NN*8 exactly
    int n = idx >> 3, c = idx & 7;              // c: 8-col chunk
    if (n >= NN) return;
    int beg = g_rowptr[n], end = g_rowptr[n + 1];
    const float4* h4 = (const float4*)g_h;
    const uint4* hb = (const uint4*)g_hb;       // 8 uint4 per row
    float4 v0 = h4[(size_t)n * 16 + c * 2];     // self term fp32-exact
    float4 v1 = h4[(size_t)n * 16 + c * 2 + 1];
    int p = beg;
    for (; p + 4 <= end; p += 4) {
        int s0 = g_esrc[p];
        int s1 = g_esrc[p + 1];
        int s2 = g_esrc[p + 2];
        int s3 = g_esrc[p + 3];
        uint4 a0 = hb[(size_t)s0 * 8 + c];
        uint4 a1 = hb[(size_t)s1 * 8 + c];
        uint4 a2 = hb[(size_t)s2 * 8 + c];
        uint4 a3 = hb[(size_t)s3 * 8 + c];
        acc8(v0, v1, a0);
        acc8(v0, v1, a1);
        acc8(v0, v1, a2);
        acc8(v0, v1, a3);
    }
    for (; p < end; p++) {
        uint4 a0 = hb[(size_t)g_esrc[p] * 8 + c];
        acc8(v0, v1, a0);
    }
    float4* o = (float4*)g_agg;
    o[(size_t)n * 16 + c * 2]     = v0;
    o[(size_t)n * 16 + c * 2 + 1] = v1;
}

// Zs layout: row r at floats [r*64, r*64+64); col k stored at slot
// ((k + 4*(r>>2)) & 63). Rotation multiple of 4 floats keeps float4 alignment
// AND keeps k-quads contiguous; the 4 row-groups in a warp differ by 4 banks.

// 16 ffma2: one k-column of 4 z values against the 8-wide w pair
#define FF4(za, zb, zc, zd, wa, wb)                              \
    {                                                            \
        u64 z0p = pack2(za, za), z1p = pack2(zb, zb);            \
        u64 z2p = pack2(zc, zc), z3p = pack2(zd, zd);            \
        ffma2(acc[0][0], z0p, wa.x); ffma2(acc[0][1], z0p, wa.y);\
        ffma2(acc[0][2], z0p, wb.x); ffma2(acc[0][3], z0p, wb.y);\
        ffma2(acc[1][0], z1p, wa.x); ffma2(acc[1][1], z1p, wa.y);\
        ffma2(acc[1][2], z1p, wb.x); ffma2(acc[1][3], z1p, wb.y);\
        ffma2(acc[2][0], z2p, wa.x); ffma2(acc[2][1], z2p, wa.y);\
        ffma2(acc[2][2], z2p, wb.x); ffma2(acc[2][3], z2p, wb.y);\
        ffma2(acc[3][0], z3p, wa.x); ffma2(acc[3][1], z3p, wa.y);\
        ffma2(acc[3][2], z3p, wb.x); ffma2(acc[3][3], z3p, wb.y);\
    }

// inner loop over 16 k-quads: 4 z LDS.128 + 8 w LDS.128 + 64 ffma2 per quad
#define GEMM_CORE(accinit)                                                  \
    u64 acc[4][4];                                                          \
    _Pragma("unroll")                                                       \
    for (int c = 0; c < 4; c++)                                             \
        _Pragma("unroll")                                                   \
        for (int j = 0; j < 4; j++) acc[j][c] = (accinit)[c];               \
    {                                                                       \
        const ulonglong2* Wsu = (const ulonglong2*)Ws;                      \
        _Pragma("unroll 4")                                                 \
        for (int kq = 0; kq < 16; kq++) {                                   \
            int base = (kq * 4 + 4 * g) & 63;                               \
            float4 zq0 = *(const float4*)(Zs + (rowb + 0) * 64 + base);     \
            float4 zq1 = *(const float4*)(Zs + (rowb + 1) * 64 + base);     \
            float4 zq2 = *(const float4*)(Zs + (rowb + 2) * 64 + base);     \
            float4 zq3 = *(const float4*)(Zs + (rowb + 3) * 64 + base);     \
            int k0 = kq * 4;                                                \
            ulonglong2 wa = Wsu[k0 * 16 + cw * 2];                          \
            ulonglong2 wb = Wsu[k0 * 16 + cw * 2 + 1];                      \
            FF4(zq0.x, zq1.x, zq2.x, zq3.x, wa, wb);                        \
            wa = Wsu[(k0 + 1) * 16 + cw * 2];                               \
            wb = Wsu[(k0 + 1) * 16 + cw * 2 + 1];                           \
            FF4(zq0.y, zq1.y, zq2.y, zq3.y, wa, wb);                        \
            wa = Wsu[(k0 + 2) * 16 + cw * 2];                               \
            wb = Wsu[(k0 + 2) * 16 + cw * 2 + 1];                           \
            FF4(zq0.z, zq1.z, zq2.z, zq3.z, wa, wb);                        \
            wa = Wsu[(k0 + 3) * 16 + cw * 2];                               \
            wb = Wsu[(k0 + 3) * 16 + cw * 2 + 1];                           \
            FF4(zq0.w, zq1.w, zq2.w, zq3.w, wa, wb);                        \
        }                                                                   \
    }

// ---------------- GEMM1 (persistent, 2 tiles/block): z1 = agg @ W1 + b1 + BN stats
__global__ __launch_bounds__(GT, 6) void gemm1_kernel(const float* __restrict__ W,
                                                      const float* __restrict__ b,
                                                      int layer) {
    extern __shared__ float smp[];
    float* Ws = smp;          // 4096 floats
    float* Zs = smp + 4096;   // 4096 floats
    int t = threadIdx.x;

    const float4* Wg = (const float4*)W;
    float4* Ws4 = (float4*)Ws;
#pragma unroll
    for (int i = 0; i < 8; i++) Ws4[t + i * GT] = Wg[t + i * GT];

    int cw = t & 7;            // col group: cols cw*8 .. cw*8+7
    int g  = t >> 3;           // row group 0..15: rows g*4 .. g*4+3
    int rowb = g * 4;
    u64 bp[4];
#pragma unroll
    for (int c = 0; c < 4; c++) bp[c] = pack2(b[cw * 8 + c * 2], b[cw * 8 + c * 2 + 1]);

    int colS = t & 63, half = t >> 6;
    float ssum = 0.f, sq = 0.f;   // BN partials across tiles

    for (int tile = 0; tile < TPB; tile++) {
        int row0 = (blockIdx.x * TPB + tile) * ROWS;
        __syncthreads();
#pragma unroll
        for (int i = 0; i < 8; i++) {
            int e = t + i * GT;
            int r = e >> 4, c4 = e & 15;
            int gr = row0 + r;
            float4 v = make_float4(0.f, 0.f, 0.f, 0.f);
            if (gr < NN) v = ((const float4*)g_agg)[(size_t)gr * 16 + c4];
            ((float4*)(Zs + r * 64))[(c4 + (r >> 2)) & 15] = v;
        }
        __syncthreads();

        GEMM_CORE(bp)
        __syncthreads();   // done reading Zs; reuse it for outputs

#pragma unroll
        for (int j = 0; j < 4; j++) {
            int r = rowb + j;
            int gr = row0 + r;
            float2 p0 = unpack2(acc[j][0]), p1 = unpack2(acc[j][1]);
            float2 p2 = unpack2(acc[j][2]), p3 = unpack2(acc[j][3]);
            float4 o0 = make_float4(p0.x, p0.y, p1.x, p1.y);
            float4 o1 = make_float4(p2.x, p2.y, p3.x, p3.y);
            if (gr < NN) {
                float4* og = (float4*)(g_z1 + (size_t)gr * 64 + cw * 8);
                og[0] = o0; og[1] = o1;
            } else {
                o0 = make_float4(0.f, 0.f, 0.f, 0.f);
                o1 = o0;
            }
            float4* zr = (float4*)(Zs + r * 64);
            zr[(cw * 2 + g) & 15]     = o0;
            zr[(cw * 2 + 1 + g) & 15] = o1;
        }
        __syncthreads();

#pragma unroll 8
        for (int r = half * 32; r < half * 32 + 32; r++) {
            float v = Zs[r * 64 + ((colS + 4 * (r >> 2)) & 63)];
            ssum += v;
            sq += v * v;
        }
    }
    atomicAdd(&g_bnsum[layer * 64 + colS], ssum);
    atomicAdd(&g_bnsq[layer * 64 + colS], sq);
}

// ---------------- GEMM2 (persistent): h(+bf16 mirror) = relu(bn(z1)) @ W2 + b2 + pool
// BN=false is the embedding GEMM: h = x @ W_emb + b_emb
template <bool BN>
__global__ __launch_bounds__(GT, 6) void gemm2_kernel(const float* __restrict__ in,
                             const float* __restrict__ W, const float* __restrict__ b,
                             const float* __restrict__ gamma, const float* __restrict__ beta,
                             const int* __restrict__ batch, int pool_off, int layer) {
    extern __shared__ float smp[];
    float* Ws = smp;            // 4096
    float* Zs = smp + 4096;     // 4096
    float* sc = smp + 8192;     // 64
    float* sh = smp + 8256;     // 64
    int*   sb = (int*)(smp + 8320);  // 64
    int t = threadIdx.x;

    if (t < 64 && BN) {
        float mu = g_bnsum[layer * 64 + t] * (1.f / NN);
        float var = g_bnsq[layer * 64 + t] * (1.f / NN) - mu * mu;
        float rs = rsqrtf(var + 1e-5f);
        float s = gamma[t] * rs;
        sc[t] = s;
        sh[t] = beta[t] - mu * s;
    }
    const float4* Wg = (const float4*)W;
    float4* Ws4 = (float4*)Ws;
#pragma unroll
    for (int i = 0; i < 8; i++) Ws4[t + i * GT] = Wg[t + i * GT];

    int cw = t & 7;
    int g  = t >> 3;
    int rowb = g * 4;
    u64 bp[4];
#pragma unroll
    for (int c = 0; c < 4; c++) bp[c] = pack2(b[cw * 8 + c * 2], b[cw * 8 + c * 2 + 1]);

    for (int tile = 0; tile < TPB; tile++) {
        int row0 = (blockIdx.x * TPB + tile) * ROWS;
        __syncthreads();   // covers Ws/sc/sh (iter 0) and prior pool reads (iter>0)
        if (t < ROWS) {
            int gr = row0 + t;
            sb[t] = (gr < NN) ? batch[gr] : -1;
        }
#pragma unroll
        for (int i = 0; i < 8; i++) {
            int e = t + i * GT;
            int r = e >> 4, c4 = e & 15;
            int gr = row0 + r;
            float4 v = make_float4(0.f, 0.f, 0.f, 0.f);
            if (gr < NN) {
                v = ((const float4*)in)[(size_t)gr * 16 + c4];
                if (BN) {
                    int k = c4 * 4;
                    v.x = fmaxf(v.x * sc[k]     + sh[k],     0.f);
                    v.y = fmaxf(v.y * sc[k + 1] + sh[k + 1], 0.f);
                    v.z = fmaxf(v.z * sc[k + 2] + sh[k + 2], 0.f);
                    v.w = fmaxf(v.w * sc[k + 3] + sh[k + 3], 0.f);
                }
            }
            ((float4*)(Zs + r * 64))[(c4 + (r >> 2)) & 15] = v;
        }
        __syncthreads();

        GEMM_CORE(bp)
        __syncthreads();

#pragma unroll
        for (int j = 0; j < 4; j++) {
            int r = rowb + j;
            int gr = row0 + r;
            float2 p0 = unpack2(acc[j][0]), p1 = unpack2(acc[j][1]);
            float2 p2 = unpack2(acc[j][2]), p3 = unpack2(acc[j][3]);
            float4 o0 = make_float4(p0.x, p0.y, p1.x, p1.y);
            float4 o1 = make_float4(p2.x, p2.y, p3.x, p3.y);
            if (gr < NN) {
                float4* og = (float4*)(g_h + (size_t)gr * 64 + cw * 8);
                og[0] = o0; og[1] = o1;
                // bf16 mirror for the gather
                __nv_bfloat162 h0 = __float22bfloat162_rn(make_float2(o0.x, o0.y));
                __nv_bfloat162 h1 = __float22bfloat162_rn(make_float2(o0.z, o0.w));
                __nv_bfloat162 h2 = __float22bfloat162_rn(make_float2(o1.x, o1.y));
                __nv_bfloat162 h3 = __float22bfloat162_rn(make_float2(o1.z, o1.w));
                uint4 u;
                u.x = *(u32*)&h0; u.y = *(u32*)&h1;
                u.z = *(u32*)&h2; u.w = *(u32*)&h3;
                *(uint4*)(g_hb + (size_t)gr * 64 + cw * 8) = u;
            } else {
                o0 = make_float4(0.f, 0.f, 0.f, 0.f);
                o1 = o0;
            }
            float4* zr = (float4*)(Zs + r * 64);
            zr[(cw * 2 + g) & 15]     = o0;
            zr[(cw * 2 + 1 + g) & 15] = o1;
        }
        __syncthreads();

        // segmented mean-pool accumulation (batch sorted -> few runs per block)
        if (t < 64) {
            float s = 0.f;
            int cur = sb[0];
            for (int r = 0; r < ROWS; r++) {
                int g2 = sb[r];
                if (g2 != cur) {
                    if (cur >= 0) atomicAdd(&g_pool[cur * OUTC + pool_off + t], s);
                    s = 0.f;
                    cur = g2;
                }
                s += Zs[r * 64 + ((t + 4 * (r >> 2)) & 63)];
            }
            if (cur >= 0) atomicAdd(&g_pool[cur * OUTC + pool_off + t], s);
        }
    }
}

__global__ void finalize_kernel(float* __restrict__ out) {
    int i = blockIdx.x * 256 + threadIdx.x;
    if (i < GG * OUTC) {
        int g = i / OUTC;
        float c = (float)max(g_cnt[g], 1);
        out[i] = g_pool[i] / c;
    }
}

// ---------------- host ----------------
extern "C" void kernel_launch(void* const* d_in, const int* in_sizes, int n_in,
                              void* d_out, int out_size) {
    const float* x     = (const float*)d_in[0];
    const int*   ei    = (const int*)d_in[1];
    const int*   batch = (const int*)d_in[2];
    const float* W_emb = (const float*)d_in[3];
    const float* b_emb = (const float*)d_in[4];
    const float* W1    = (const float*)d_in[5];
    const float* b1    = (const float*)d_in[6];
    const float* gamma = (const float*)d_in[7];
    const float* beta  = (const float*)d_in[8];
    const float* W2    = (const float*)d_in[9];
    const float* b2    = (const float*)d_in[10];
    float* out = (float*)d_out;

    // persistent side-stream + events (host resources only; created once)
    static cudaStream_t sB = nullptr;
    static cudaEvent_t evFork = nullptr, evJoin = nullptr;
    if (sB == nullptr) {
        cudaStreamCreateWithFlags(&sB, cudaStreamNonBlocking);
        cudaEventCreateWithFlags(&evFork, cudaEventDisableTiming);
        cudaEventCreateWithFlags(&evJoin, cudaEventDisableTiming);
    }

    cudaFuncSetAttribute(gemm1_kernel, cudaFuncAttributeMaxDynamicSharedMemorySize, SMEM_G);
    cudaFuncSetAttribute(gemm2_kernel<false>, cudaFuncAttributeMaxDynamicSharedMemorySize, SMEM_G);
    cudaFuncSetAttribute(gemm2_kernel<true>, cudaFuncAttributeMaxDynamicSharedMemorySize, SMEM_G);

    void* p_z1;
    cudaGetSymbolAddress(&p_z1, g_z1);

    clear_kernel<<<(NN + 255) / 256, 256>>>();

    // fork: embedding GEMM (independent of CSR build) on side stream
    cudaEventRecord(evFork, 0);
    cudaStreamWaitEvent(sB, evFork, 0);
    gemm2_kernel<false><<<GBP, GT, SMEM_G, sB>>>(x, W_emb, b_emb, nullptr, nullptr,
                                                 batch, 0, 0);
    cudaEventRecord(evJoin, sB);

    // CSR build on the main stream, concurrent with the embedding GEMM
    count_deg_kernel<<<(EE + 255) / 256, 256>>>(batch, ei);
    scan1_kernel<<<NB, 1024>>>();
    scan23_kernel<<<NB, 1024>>>();
    fill_kernel<<<(EE + 255) / 256, 256>>>(ei);

    // join: layer loop needs both g_h/g_hb (embedding) and g_esrc (CSR)
    cudaStreamWaitEvent(0, evJoin, 0);

    for (int l = 0; l < 4; l++) {
        gather_kernel<<<(NN * 8 + 255) / 256, 256>>>();
        gemm1_kernel<<<GBP, GT, SMEM_G>>>(W1 + l * 4096, b1 + l * 64, l);
        gemm2_kernel<true><<<GBP, GT, SMEM_G>>>((const float*)p_z1, W2 + l * 4096, b2 + l * 64,
                                        gamma + l * 64, beta + l * 64, batch,
                                        (l + 1) * 64, l);
    }

    finalize_kernel<<<(GG * OUTC + 255) / 256, 256>>>(out);
}

// round 15
// speedup vs baseline: 1.2630x; 1.0943x over previous
#include <cuda_runtime.h>
#include <cuda_bf16.h>

#define NN 100000
#define EE 1200000
#define GG 128
#define OUTC 320        // 64*(4+1)
#define ROWS 64         // rows per GEMM tile
#define GT 128          // threads per GEMM block
#define TPB 2           // tiles per persistent GEMM block
#define GBP 782         // GEMM grid: 782*2 = 1564 tiles >= 1563
#define SMEM_G 33536    // (4096 + 4096 + 64 + 64 + 64) floats * 4
#define NB 98           // scan blocks = ceil(NN/1024)
#define GA 3125         // gather grid: NN*8/256

typedef unsigned long long u64;
typedef unsigned int u32;

// ---------------- scratch (static __device__, no allocation) ----------------
__device__ __align__(128) __nv_bfloat16 g_u[NN * 64];  // u = h @ W1_next (bf16)
__device__ __align__(128) float g_z1[NN * 64];
__device__ int   g_esrc[EE];
__device__ int   g_rowptr[NN + 1];
__device__ int   g_cursor[NN];
__device__ int   g_deg[NN];
__device__ int   g_bsum[NB];
__device__ float g_pool[GG * OUTC];
__device__ int   g_cnt[GG];
__device__ float g_bnsum[4 * 64];
__device__ float g_bnsq[4 * 64];

// ---------------- packed f32x2 helpers ----------------
__device__ __forceinline__ u64 pack2(float x, float y) {
    u64 r; asm("mov.b64 %0, {%1, %2};" : "=l"(r) : "f"(x), "f"(y)); return r;
}
__device__ __forceinline__ void ffma2(u64& d, u64 a, u64 b) {
    asm("fma.rn.f32x2 %0, %1, %2, %0;" : "+l"(d) : "l"(a), "l"(b));
}
__device__ __forceinline__ float2 unpack2(u64 v) {
    float2 f; asm("mov.b64 {%0, %1}, %2;" : "=f"(f.x), "=f"(f.y) : "l"(v)); return f;
}

// ---------------- one kernel clears all small scratch ----------------
__global__ void clear_kernel() {
    int i = blockIdx.x * 256 + threadIdx.x;
    if (i < GG * OUTC) g_pool[i] = 0.f;
    if (i < GG) g_cnt[i] = 0;
    if (i < NN) g_deg[i] = 0;
    if (i < 4 * 64) { g_bnsum[i] = 0.f; g_bnsq[i] = 0.f; }
}

// ---------------- fused: per-graph node counts + in-degree histogram ----------
__global__ void count_deg_kernel(const int* __restrict__ batch,
                                 const int* __restrict__ ei) {
    int i = blockIdx.x * 256 + threadIdx.x;
    if (i < NN) atomicAdd(&g_cnt[batch[i]], 1);
    if (i < EE) atomicAdd(&g_deg[ei[EE + i]], 1);
}

// ---------------- CSR build ----------------
__global__ void scan1_kernel() {
    __shared__ int s[1024];
    int t = threadIdx.x;
    int i = blockIdx.x * 1024 + t;
    int x = (i < NN) ? g_deg[i] : 0;
    s[t] = x;
    __syncthreads();
#pragma unroll
    for (int off = 1; off < 1024; off <<= 1) {
        int v = (t >= off) ? s[t - off] : 0;
        __syncthreads();
        s[t] += v;
        __syncthreads();
    }
    if (i < NN) g_rowptr[i] = s[t] - x;      // exclusive, partial
    if (t == 1023) g_bsum[blockIdx.x] = s[1023];
}

__global__ void scan23_kernel() {
    __shared__ int sm[128];
    int t = threadIdx.x;
    int b = blockIdx.x;
    if (t < 128) sm[t] = (t < b && t < NB) ? g_bsum[t] : 0;
    __syncthreads();
#pragma unroll
    for (int off = 64; off >= 1; off >>= 1) {
        if (t < off) sm[t] += sm[t + off];
        __syncthreads();
    }
    int prefix = sm[0];
    int i = b * 1024 + t;
    if (i < NN) {
        int v = g_rowptr[i] + prefix;
        g_rowptr[i] = v;
        g_cursor[i] = v;
    }
    if (i == 0) g_rowptr[NN] = EE;
}

__global__ void fill_kernel(const int* __restrict__ ei) {
    int e = blockIdx.x * 256 + threadIdx.x;
    if (e < EE) {
        int dst = ei[EE + e];
        int pos = atomicAdd(&g_cursor[dst], 1);
        g_esrc[pos] = ei[e];
    }
}

// ---------------- bf16 octet accumulate ----------------
__device__ __forceinline__ void acc8(float4& v0, float4& v1, uint4 a) {
    v0.x += __uint_as_float(a.x << 16);
    v0.y += __uint_as_float(a.x & 0xFFFF0000u);
    v0.z += __uint_as_float(a.y << 16);
    v0.w += __uint_as_float(a.y & 0xFFFF0000u);
    v1.x += __uint_as_float(a.z << 16);
    v1.y += __uint_as_float(a.z & 0xFFFF0000u);
    v1.z += __uint_as_float(a.w << 16);
    v1.w += __uint_as_float(a.w & 0xFFFF0000u);
}

// ---------------- gather: z1[n] = u[n] + sum_{s in N(n)} u[s] + b1, + BN stats
// 8 threads per node, 8 columns each; 4-edge unroll; in-kernel stat reduction
__global__ void gather_kernel(const float* __restrict__ b1, int layer) {
    __shared__ float red[8][8][16];   // 8 warps per 256-thread block
    int t = threadIdx.x;
    int idx = blockIdx.x * 256 + t;       // grid covers NN*8 exactly
    int n = idx >> 3, c = idx & 7;
    int w = t >> 5, lane = t & 31;
    int beg = g_rowptr[n], end = g_rowptr[n + 1];
    const uint4* ub = (const uint4*)g_u;

    float4 v0 = *(const float4*)(b1 + c * 8);       // bias
    float4 v1 = *(const float4*)(b1 + c * 8 + 4);
    acc8(v0, v1, ub[(size_t)n * 8 + c]);            // self term
    int p = beg;
    for (; p + 4 <= end; p += 4) {
        int s0 = g_esrc[p];
        int s1 = g_esrc[p + 1];
        int s2 = g_esrc[p + 2];
        int s3 = g_esrc[p + 3];
        uint4 a0 = ub[(size_t)s0 * 8 + c];
        uint4 a1 = ub[(size_t)s1 * 8 + c];
        uint4 a2 = ub[(size_t)s2 * 8 + c];
        uint4 a3 = ub[(size_t)s3 * 8 + c];
        acc8(v0, v1, a0);
        acc8(v0, v1, a1);
        acc8(v0, v1, a2);
        acc8(v0, v1, a3);
    }
    for (; p < end; p++) acc8(v0, v1, ub[(size_t)g_esrc[p] * 8 + c]);

    float4* o = (float4*)g_z1;
    o[(size_t)n * 16 + c * 2]     = v0;
    o[(size_t)n * 16 + c * 2 + 1] = v1;

    // BN stats: butterfly over the 4 nodes sharing chunk c within this warp
    float st[16] = { v0.x, v0.y, v0.z, v0.w, v1.x, v1.y, v1.z, v1.w,
                     v0.x * v0.x, v0.y * v0.y, v0.z * v0.z, v0.w * v0.w,
                     v1.x * v1.x, v1.y * v1.y, v1.z * v1.z, v1.w * v1.w };
#pragma unroll
    for (int k = 0; k < 16; k++) {
        st[k] += __shfl_xor_sync(0xFFFFFFFFu, st[k], 8);
        st[k] += __shfl_xor_sync(0xFFFFFFFFu, st[k], 16);
    }
    if (lane < 8) {
#pragma unroll
        for (int k = 0; k < 16; k++) red[w][lane][k] = st[k];
    }
    __syncthreads();
    if (t < 128) {
        int which = t >> 6;            // 0 = sum, 1 = sumsq
        int col = t & 63;
        int cc = col >> 3, j = col & 7;
        float r = 0.f;
#pragma unroll
        for (int ww = 0; ww < 8; ww++) r += red[ww][cc][which * 8 + j];
        if (which == 0) atomicAdd(&g_bnsum[layer * 64 + col], r);
        else            atomicAdd(&g_bnsq[layer * 64 + col], r);
    }
}

// Zs layout: row r at floats [r*64, r*64+64); col k stored at slot
// ((k + 4*(r>>2)) & 63). Rotation multiple of 4 floats keeps float4 alignment
// AND keeps k-quads contiguous; the 4 row-groups in a warp differ by 4 banks.

#define FF4(za, zb, zc, zd, wa, wb)                              \
    {                                                            \
        u64 z0p = pack2(za, za), z1p = pack2(zb, zb);            \
        u64 z2p = pack2(zc, zc), z3p = pack2(zd, zd);            \
        ffma2(acc[0][0], z0p, wa.x); ffma2(acc[0][1], z0p, wa.y);\
        ffma2(acc[0][2], z0p, wb.x); ffma2(acc[0][3], z0p, wb.y);\
        ffma2(acc[1][0], z1p, wa.x); ffma2(acc[1][1], z1p, wa.y);\
        ffma2(acc[1][2], z1p, wb.x); ffma2(acc[1][3], z1p, wb.y);\
        ffma2(acc[2][0], z2p, wa.x); ffma2(acc[2][1], z2p, wa.y);\
        ffma2(acc[2][2], z2p, wb.x); ffma2(acc[2][3], z2p, wb.y);\
        ffma2(acc[3][0], z3p, wa.x); ffma2(acc[3][1], z3p, wa.y);\
        ffma2(acc[3][2], z3p, wb.x); ffma2(acc[3][3], z3p, wb.y);\
    }

#define GEMM_CORE(accinit)                                                  \
    u64 acc[4][4];                                                          \
    _Pragma("unroll")                                                       \
    for (int c = 0; c < 4; c++)                                             \
        _Pragma("unroll")                                                   \
        for (int j = 0; j < 4; j++) acc[j][c] = (accinit)[c];               \
    {                                                                       \
        const ulonglong2* Wsu = (const ulonglong2*)Ws;                      \
        _Pragma("unroll 4")                                                 \
        for (int kq = 0; kq < 16; kq++) {                                   \
            int base = (kq * 4 + 4 * g) & 63;                               \
            float4 zq0 = *(const float4*)(Zs + (rowb + 0) * 64 + base);     \
            float4 zq1 = *(const float4*)(Zs + (rowb + 1) * 64 + base);     \
            float4 zq2 = *(const float4*)(Zs + (rowb + 2) * 64 + base);     \
            float4 zq3 = *(const float4*)(Zs + (rowb + 3) * 64 + base);     \
            int k0 = kq * 4;                                                \
            ulonglong2 wa = Wsu[k0 * 16 + cw * 2];                          \
            ulonglong2 wb = Wsu[k0 * 16 + cw * 2 + 1];                      \
            FF4(zq0.x, zq1.x, zq2.x, zq3.x, wa, wb);                        \
            wa = Wsu[(k0 + 1) * 16 + cw * 2];                               \
            wb = Wsu[(k0 + 1) * 16 + cw * 2 + 1];                           \
            FF4(zq0.y, zq1.y, zq2.y, zq3.y, wa, wb);                        \
            wa = Wsu[(k0 + 2) * 16 + cw * 2];                               \
            wb = Wsu[(k0 + 2) * 16 + cw * 2 + 1];                           \
            FF4(zq0.z, zq1.z, zq2.z, zq3.z, wa, wb);                        \
            wa = Wsu[(k0 + 3) * 16 + cw * 2];                               \
            wb = Wsu[(k0 + 3) * 16 + cw * 2 + 1];                           \
            FF4(zq0.w, zq1.w, zq2.w, zq3.w, wa, wb);                        \
        }                                                                   \
    }

// ---------------- fused layer kernel (persistent, 2 tiles/block) -------------
// BN=true:  m = relu(bn(z1)); h = m @ W2 + b2; pool h; if NEXT: u = h @ Wn (bf16)
// BN=false: h = x @ W_emb + b_emb; pool h; u = h @ W1[0] (embedding)
template <bool BN, bool NEXT>
__global__ __launch_bounds__(GT, 6) void fused_kernel(const float* __restrict__ in,
                             const float* __restrict__ W, const float* __restrict__ b,
                             const float* __restrict__ Wn,
                             const float* __restrict__ gamma, const float* __restrict__ beta,
                             const int* __restrict__ batch, int pool_off, int layer) {
    extern __shared__ float smp[];
    float* Ws = smp;            // 4096
    float* Zs = smp + 4096;     // 4096
    float* sc = smp + 8192;     // 64
    float* sh = smp + 8256;     // 64
    int*   sb = (int*)(smp + 8320);  // 64
    int t = threadIdx.x;

    if (t < 64 && BN) {
        float mu = g_bnsum[layer * 64 + t] * (1.f / NN);
        float var = g_bnsq[layer * 64 + t] * (1.f / NN) - mu * mu;
        float rs = rsqrtf(var + 1e-5f);
        float s = gamma[t] * rs;
        sc[t] = s;
        sh[t] = beta[t] - mu * s;
    }
    int cw = t & 7;
    int g  = t >> 3;
    int rowb = g * 4;
    u64 bp[4];
#pragma unroll
    for (int c = 0; c < 4; c++) bp[c] = pack2(b[cw * 8 + c * 2], b[cw * 8 + c * 2 + 1]);
    u64 zp[4] = {0, 0, 0, 0};

    const float4* Wg = (const float4*)W;
    const float4* Wng = (const float4*)Wn;
    float4* Ws4 = (float4*)Ws;

    for (int tile = 0; tile < TPB; tile++) {
        int row0 = (blockIdx.x * TPB + tile) * ROWS;
        __syncthreads();   // prior tile's Zs/Ws reads done (and sc/sh on iter 0)
        if (t < ROWS) {
            int gr = row0 + t;
            sb[t] = (gr < NN) ? batch[gr] : -1;
        }
#pragma unroll
        for (int i = 0; i < 8; i++) Ws4[t + i * GT] = Wg[t + i * GT];
#pragma unroll
        for (int i = 0; i < 8; i++) {
            int e = t + i * GT;
            int r = e >> 4, c4 = e & 15;
            int gr = row0 + r;
            float4 v = make_float4(0.f, 0.f, 0.f, 0.f);
            if (gr < NN) {
                v = ((const float4*)in)[(size_t)gr * 16 + c4];
                if (BN) {
                    int k = c4 * 4;
                    v.x = fmaxf(v.x * sc[k]     + sh[k],     0.f);
                    v.y = fmaxf(v.y * sc[k + 1] + sh[k + 1], 0.f);
                    v.z = fmaxf(v.z * sc[k + 2] + sh[k + 2], 0.f);
                    v.w = fmaxf(v.w * sc[k + 3] + sh[k + 3], 0.f);
                }
            }
            ((float4*)(Zs + r * 64))[(c4 + (r >> 2)) & 15] = v;
        }
        __syncthreads();   // A: Zs (input) + Ws (W) ready

        {   // core 1: h = Zs @ W + b
            GEMM_CORE(bp)
            __syncthreads();   // B: all reads of Zs/Ws done
#pragma unroll
            for (int j = 0; j < 4; j++) {
                int r = rowb + j;
                int gr = row0 + r;
                float2 p0 = unpack2(acc[j][0]), p1 = unpack2(acc[j][1]);
                float2 p2 = unpack2(acc[j][2]), p3 = unpack2(acc[j][3]);
                float4 o0 = make_float4(p0.x, p0.y, p1.x, p1.y);
                float4 o1 = make_float4(p2.x, p2.y, p3.x, p3.y);
                if (gr >= NN) { o0 = make_float4(0.f, 0.f, 0.f, 0.f); o1 = o0; }
                float4* zr = (float4*)(Zs + r * 64);
                zr[(cw * 2 + g) & 15]     = o0;
                zr[(cw * 2 + 1 + g) & 15] = o1;
            }
            if (NEXT) {   // reload Ws with W1_next while Zs fills with h
#pragma unroll
                for (int i = 0; i < 8; i++) Ws4[t + i * GT] = Wng[t + i * GT];
            }
        }
        __syncthreads();   // C: Zs = h, Ws = Wn ready

        if (NEXT) {   // core 2: u = h @ Wn, bf16 out
            GEMM_CORE(zp)
#pragma unroll
            for (int j = 0; j < 4; j++) {
                int gr = row0 + rowb + j;
                if (gr < NN) {
                    float2 p0 = unpack2(acc[j][0]), p1 = unpack2(acc[j][1]);
                    float2 p2 = unpack2(acc[j][2]), p3 = unpack2(acc[j][3]);
                    __nv_bfloat162 h0 = __float22bfloat162_rn(p0);
                    __nv_bfloat162 h1 = __float22bfloat162_rn(p1);
                    __nv_bfloat162 h2 = __float22bfloat162_rn(p2);
                    __nv_bfloat162 h3 = __float22bfloat162_rn(p3);
                    uint4 u;
                    u.x = *(u32*)&h0; u.y = *(u32*)&h1;
                    u.z = *(u32*)&h2; u.w = *(u32*)&h3;
                    *(uint4*)(g_u + (size_t)gr * 64 + cw * 8) = u;
                }
            }
        }

        // segmented mean-pool over h (Zs); batch sorted -> few runs per block
        if (t < 64) {
            float s = 0.f;
            int cur = sb[0];
            for (int r = 0; r < ROWS; r++) {
                int g2 = sb[r];
                if (g2 != cur) {
                    if (cur >= 0) atomicAdd(&g_pool[cur * OUTC + pool_off + t], s);
                    s = 0.f;
                    cur = g2;
                }
                s += Zs[r * 64 + ((t + 4 * (r >> 2)) & 63)];
            }
            if (cur >= 0) atomicAdd(&g_pool[cur * OUTC + pool_off + t], s);
        }
    }
}

__global__ void finalize_kernel(float* __restrict__ out) {
    int i = blockIdx.x * 256 + threadIdx.x;
    if (i < GG * OUTC) {
        int g = i / OUTC;
        float c = (float)max(g_cnt[g], 1);
        out[i] = g_pool[i] / c;
    }
}

// ---------------- host ----------------
extern "C" void kernel_launch(void* const* d_in, const int* in_sizes, int n_in,
                              void* d_out, int out_size) {
    const float* x     = (const float*)d_in[0];
    const int*   ei    = (const int*)d_in[1];
    const int*   batch = (const int*)d_in[2];
    const float* W_emb = (const float*)d_in[3];
    const float* b_emb = (const float*)d_in[4];
    const float* W1    = (const float*)d_in[5];
    const float* b1    = (const float*)d_in[6];
    const float* gamma = (const float*)d_in[7];
    const float* beta  = (const float*)d_in[8];
    const float* W2    = (const float*)d_in[9];
    const float* b2    = (const float*)d_in[10];
    float* out = (float*)d_out;

    // persistent side-stream + events (host resources only; created once)
    static cudaStream_t sB = nullptr;
    static cudaEvent_t evFork = nullptr, evJoin = nullptr;
    if (sB == nullptr) {
        cudaStreamCreateWithFlags(&sB, cudaStreamNonBlocking);
        cudaEventCreateWithFlags(&evFork, cudaEventDisableTiming);
        cudaEventCreateWithFlags(&evJoin, cudaEventDisableTiming);
    }

    cudaFuncSetAttribute(fused_kernel<false, true>,
                         cudaFuncAttributeMaxDynamicSharedMemorySize, SMEM_G);
    cudaFuncSetAttribute(fused_kernel<true, true>,
                         cudaFuncAttributeMaxDynamicSharedMemorySize, SMEM_G);
    cudaFuncSetAttribute(fused_kernel<true, false>,
                         cudaFuncAttributeMaxDynamicSharedMemorySize, SMEM_G);

    void* p_z1;
    cudaGetSymbolAddress(&p_z1, g_z1);

    clear_kernel<<<(NN + 255) / 256, 256>>>();

    // fork: embedding (x@W_emb+b_emb, pool, u0 = emb@W1[0]) on side stream
    cudaEventRecord(evFork, 0);
    cudaStreamWaitEvent(sB, evFork, 0);
    fused_kernel<false, true><<<GBP, GT, SMEM_G, sB>>>(x, W_emb, b_emb, W1,
                                                       nullptr, nullptr, batch, 0, 0);
    cudaEventRecord(evJoin, sB);

    // CSR build on the main stream, concurrent with the embedding
    count_deg_kernel<<<(EE + 255) / 256, 256>>>(batch, ei);
    scan1_kernel<<<NB, 1024>>>();
    scan23_kernel<<<NB, 1024>>>();
    fill_kernel<<<(EE + 255) / 256, 256>>>(ei);

    // join: layer loop needs both g_u (embedding) and g_esrc (CSR)
    cudaStreamWaitEvent(0, evJoin, 0);

    for (int l = 0; l < 4; l++) {
        gather_kernel<<<GA, 256>>>(b1 + l * 64, l);
        if (l < 3)
            fused_kernel<true, true><<<GBP, GT, SMEM_G>>>((const float*)p_z1,
                W2 + l * 4096, b2 + l * 64, W1 + (l + 1) * 4096,
                gamma + l * 64, beta + l * 64, batch, (l + 1) * 64, l);
        else
            fused_kernel<true, false><<<GBP, GT, SMEM_G>>>((const float*)p_z1,
                W2 + l * 4096, b2 + l * 64, nullptr,
                gamma + l * 64, beta + l * 64, batch, (l + 1) * 64, l);
    }

    finalize_kernel<<<(GG * OUTC + 255) / 256, 256>>>(out);
}

// round 16
// speedup vs baseline: 1.2641x; 1.0009x over previous
#include <cuda_runtime.h>
#include <cuda_bf16.h>

#define NN 100000
#define EE 1200000
#define GG 128
#define OUTC 320        // 64*(4+1)
#define ROWS 64         // rows per GEMM tile
#define GT 128          // threads per GEMM block
#define TPB 2           // tiles per persistent GEMM block
#define GBP 782         // GEMM grid: 782*2 = 1564 tiles >= 1563
#define SMEM_G 33536    // (4096 + 4096 + 64 + 64 + 64) floats * 4
#define NB 98           // scan blocks = ceil(NN/1024)
#define GA 3125         // gather grid: NN*8/256

typedef unsigned long long u64;
typedef unsigned int u32;

// ---------------- scratch (static __device__, no allocation) ----------------
__device__ __align__(128) __nv_bfloat16 g_u[NN * 64];    // u = h @ W1_next (bf16)
__device__ __align__(128) __nv_bfloat16 g_z1b[NN * 64];  // z1 (bf16)
__device__ int   g_esrc[EE];
__device__ int   g_rowptr[NN + 1];
__device__ int   g_cursor[NN];
__device__ int   g_deg[NN];
__device__ int   g_bsum[NB];
__device__ float g_pool[GG * OUTC];
__device__ int   g_cnt[GG];
__device__ float g_bnsum[4 * 64];
__device__ float g_bnsq[4 * 64];

// ---------------- packed f32x2 helpers ----------------
__device__ __forceinline__ u64 pack2(float x, float y) {
    u64 r; asm("mov.b64 %0, {%1, %2};" : "=l"(r) : "f"(x), "f"(y)); return r;
}
__device__ __forceinline__ void ffma2(u64& d, u64 a, u64 b) {
    asm("fma.rn.f32x2 %0, %1, %2, %0;" : "+l"(d) : "l"(a), "l"(b));
}
__device__ __forceinline__ float2 unpack2(u64 v) {
    float2 f; asm("mov.b64 {%0, %1}, %2;" : "=f"(f.x), "=f"(f.y) : "l"(v)); return f;
}
__device__ __forceinline__ float bf_lo(u32 a) { return __uint_as_float(a << 16); }
__device__ __forceinline__ float bf_hi(u32 a) { return __uint_as_float(a & 0xFFFF0000u); }

// ---------------- one kernel clears all small scratch ----------------
__global__ void clear_kernel() {
    int i = blockIdx.x * 256 + threadIdx.x;
    if (i < GG * OUTC) g_pool[i] = 0.f;
    if (i < GG) g_cnt[i] = 0;
    if (i < NN) g_deg[i] = 0;
    if (i < 4 * 64) { g_bnsum[i] = 0.f; g_bnsq[i] = 0.f; }
}

// ---------------- fused: per-graph node counts + in-degree histogram ----------
__global__ void count_deg_kernel(const int* __restrict__ batch,
                                 const int* __restrict__ ei) {
    int i = blockIdx.x * 256 + threadIdx.x;
    if (i < NN) atomicAdd(&g_cnt[batch[i]], 1);
    if (i < EE) atomicAdd(&g_deg[ei[EE + i]], 1);
}

// ---------------- CSR build ----------------
__global__ void scan1_kernel() {
    __shared__ int s[1024];
    int t = threadIdx.x;
    int i = blockIdx.x * 1024 + t;
    int x = (i < NN) ? g_deg[i] : 0;
    s[t] = x;
    __syncthreads();
#pragma unroll
    for (int off = 1; off < 1024; off <<= 1) {
        int v = (t >= off) ? s[t - off] : 0;
        __syncthreads();
        s[t] += v;
        __syncthreads();
    }
    if (i < NN) g_rowptr[i] = s[t] - x;      // exclusive, partial
    if (t == 1023) g_bsum[blockIdx.x] = s[1023];
}

__global__ void scan23_kernel() {
    __shared__ int sm[128];
    int t = threadIdx.x;
    int b = blockIdx.x;
    if (t < 128) sm[t] = (t < b && t < NB) ? g_bsum[t] : 0;
    __syncthreads();
#pragma unroll
    for (int off = 64; off >= 1; off >>= 1) {
        if (t < off) sm[t] += sm[t + off];
        __syncthreads();
    }
    int prefix = sm[0];
    int i = b * 1024 + t;
    if (i < NN) {
        int v = g_rowptr[i] + prefix;
        g_rowptr[i] = v;
        g_cursor[i] = v;
    }
    if (i == 0) g_rowptr[NN] = EE;
}

__global__ void fill_kernel(const int* __restrict__ ei) {
    int e = blockIdx.x * 256 + threadIdx.x;
    if (e < EE) {
        int dst = ei[EE + e];
        int pos = atomicAdd(&g_cursor[dst], 1);
        g_esrc[pos] = ei[e];
    }
}

// ---------------- bf16 octet accumulate ----------------
__device__ __forceinline__ void acc8(float4& v0, float4& v1, uint4 a) {
    v0.x += bf_lo(a.x); v0.y += bf_hi(a.x);
    v0.z += bf_lo(a.y); v0.w += bf_hi(a.y);
    v1.x += bf_lo(a.z); v1.y += bf_hi(a.z);
    v1.z += bf_lo(a.w); v1.w += bf_hi(a.w);
}

// ---------------- gather: z1[n] = u[n] + sum_{s in N(n)} u[s] + b1, + BN stats
// 8 threads per node, 8 columns each; 4-edge unroll; in-kernel stat reduction
__global__ void gather_kernel(const float* __restrict__ b1, int layer) {
    __shared__ float red[8][8][16];   // 8 warps per 256-thread block
    int t = threadIdx.x;
    int idx = blockIdx.x * 256 + t;       // grid covers NN*8 exactly
    int n = idx >> 3, c = idx & 7;
    int w = t >> 5, lane = t & 31;
    int beg = g_rowptr[n], end = g_rowptr[n + 1];
    const uint4* ub = (const uint4*)g_u;

    float4 v0 = *(const float4*)(b1 + c * 8);       // bias
    float4 v1 = *(const float4*)(b1 + c * 8 + 4);
    acc8(v0, v1, ub[(size_t)n * 8 + c]);            // self term
    int p = beg;
    for (; p + 4 <= end; p += 4) {
        int s0 = g_esrc[p];
        int s1 = g_esrc[p + 1];
        int s2 = g_esrc[p + 2];
        int s3 = g_esrc[p + 3];
        uint4 a0 = ub[(size_t)s0 * 8 + c];
        uint4 a1 = ub[(size_t)s1 * 8 + c];
        uint4 a2 = ub[(size_t)s2 * 8 + c];
        uint4 a3 = ub[(size_t)s3 * 8 + c];
        acc8(v0, v1, a0);
        acc8(v0, v1, a1);
        acc8(v0, v1, a2);
        acc8(v0, v1, a3);
    }
    for (; p < end; p++) acc8(v0, v1, ub[(size_t)g_esrc[p] * 8 + c]);

    // store z1 in bf16 (stats below stay fp32-exact)
    {
        __nv_bfloat162 z0 = __float22bfloat162_rn(make_float2(v0.x, v0.y));
        __nv_bfloat162 z1 = __float22bfloat162_rn(make_float2(v0.z, v0.w));
        __nv_bfloat162 z2 = __float22bfloat162_rn(make_float2(v1.x, v1.y));
        __nv_bfloat162 z3 = __float22bfloat162_rn(make_float2(v1.z, v1.w));
        uint4 uo;
        uo.x = *(u32*)&z0; uo.y = *(u32*)&z1;
        uo.z = *(u32*)&z2; uo.w = *(u32*)&z3;
        *(uint4*)(g_z1b + (size_t)n * 64 + c * 8) = uo;
    }

    // BN stats: butterfly over the 4 nodes sharing chunk c within this warp
    float st[16] = { v0.x, v0.y, v0.z, v0.w, v1.x, v1.y, v1.z, v1.w,
                     v0.x * v0.x, v0.y * v0.y, v0.z * v0.z, v0.w * v0.w,
                     v1.x * v1.x, v1.y * v1.y, v1.z * v1.z, v1.w * v1.w };
#pragma unroll
    for (int k = 0; k < 16; k++) {
        st[k] += __shfl_xor_sync(0xFFFFFFFFu, st[k], 8);
        st[k] += __shfl_xor_sync(0xFFFFFFFFu, st[k], 16);
    }
    if (lane < 8) {
#pragma unroll
        for (int k = 0; k < 16; k++) red[w][lane][k] = st[k];
    }
    __syncthreads();
    if (t < 128) {
        int which = t >> 6;            // 0 = sum, 1 = sumsq
        int col = t & 63;
        int cc = col >> 3, j = col & 7;
        float r = 0.f;
#pragma unroll
        for (int ww = 0; ww < 8; ww++) r += red[ww][cc][which * 8 + j];
        if (which == 0) atomicAdd(&g_bnsum[layer * 64 + col], r);
        else            atomicAdd(&g_bnsq[layer * 64 + col], r);
    }
}

// Zs layout: row r at floats [r*64, r*64+64); col k stored at slot
// ((k + 4*(r>>2)) & 63). Rotation multiple of 4 floats keeps float4 alignment
// AND keeps k-quads contiguous; the 4 row-groups in a warp differ by 4 banks.

#define FF4(za, zb, zc, zd, wa, wb)                              \
    {                                                            \
        u64 z0p = pack2(za, za), z1p = pack2(zb, zb);            \
        u64 z2p = pack2(zc, zc), z3p = pack2(zd, zd);            \
        ffma2(acc[0][0], z0p, wa.x); ffma2(acc[0][1], z0p, wa.y);\
        ffma2(acc[0][2], z0p, wb.x); ffma2(acc[0][3], z0p, wb.y);\
        ffma2(acc[1][0], z1p, wa.x); ffma2(acc[1][1], z1p, wa.y);\
        ffma2(acc[1][2], z1p, wb.x); ffma2(acc[1][3], z1p, wb.y);\
        ffma2(acc[2][0], z2p, wa.x); ffma2(acc[2][1], z2p, wa.y);\
        ffma2(acc[2][2], z2p, wb.x); ffma2(acc[2][3], z2p, wb.y);\
        ffma2(acc[3][0], z3p, wa.x); ffma2(acc[3][1], z3p, wa.y);\
        ffma2(acc[3][2], z3p, wb.x); ffma2(acc[3][3], z3p, wb.y);\
    }

#define GEMM_CORE(accinit)                                                  \
    u64 acc[4][4];                                                          \
    _Pragma("unroll")                                                       \
    for (int c = 0; c < 4; c++)                                             \
        _Pragma("unroll")                                                   \
        for (int j = 0; j < 4; j++) acc[j][c] = (accinit)[c];               \
    {                                                                       \
        const ulonglong2* Wsu = (const ulonglong2*)Ws;                      \
        _Pragma("unroll 4")                                                 \
        for (int kq = 0; kq < 16; kq++) {                                   \
            int base = (kq * 4 + 4 * g) & 63;                               \
            float4 zq0 = *(const float4*)(Zs + (rowb + 0) * 64 + base);     \
            float4 zq1 = *(const float4*)(Zs + (rowb + 1) * 64 + base);     \
            float4 zq2 = *(const float4*)(Zs + (rowb + 2) * 64 + base);     \
            float4 zq3 = *(const float4*)(Zs + (rowb + 3) * 64 + base);     \
            int k0 = kq * 4;                                                \
            ulonglong2 wa = Wsu[k0 * 16 + cw * 2];                          \
            ulonglong2 wb = Wsu[k0 * 16 + cw * 2 + 1];                      \
            FF4(zq0.x, zq1.x, zq2.x, zq3.x, wa, wb);                        \
            wa = Wsu[(k0 + 1) * 16 + cw * 2];                               \
            wb = Wsu[(k0 + 1) * 16 + cw * 2 + 1];                           \
            FF4(zq0.y, zq1.y, zq2.y, zq3.y, wa, wb);                        \
            wa = Wsu[(k0 + 2) * 16 + cw * 2];                               \
            wb = Wsu[(k0 + 2) * 16 + cw * 2 + 1];                           \
            FF4(zq0.z, zq1.z, zq2.z, zq3.z, wa, wb);                        \
            wa = Wsu[(k0 + 3) * 16 + cw * 2];                               \
            wb = Wsu[(k0 + 3) * 16 + cw * 2 + 1];                           \
            FF4(zq0.w, zq1.w, zq2.w, zq3.w, wa, wb);                        \
        }                                                                   \
    }

// ---------------- fused layer kernel (persistent, 2 tiles/block) -------------
// BN=true:  m = relu(bn(z1 bf16)); h = m @ W2 + b2; pool h; if NEXT: u = h @ Wn
// BN=false: h = x @ W_emb + b_emb; pool h; u = h @ W1[0] (embedding)
template <bool BN, bool NEXT>
__global__ __launch_bounds__(GT, 6) void fused_kernel(const float* __restrict__ in,
                             const float* __restrict__ W, const float* __restrict__ b,
                             const float* __restrict__ Wn,
                             const float* __restrict__ gamma, const float* __restrict__ beta,
                             const int* __restrict__ batch, int pool_off, int layer) {
    extern __shared__ float smp[];
    float* Ws = smp;            // 4096
    float* Zs = smp + 4096;     // 4096
    float* sc = smp + 8192;     // 64
    float* sh = smp + 8256;     // 64
    int*   sb = (int*)(smp + 8320);  // 64
    int t = threadIdx.x;

    if (t < 64 && BN) {
        float mu = g_bnsum[layer * 64 + t] * (1.f / NN);
        float var = g_bnsq[layer * 64 + t] * (1.f / NN) - mu * mu;
        float rs = rsqrtf(var + 1e-5f);
        float s = gamma[t] * rs;
        sc[t] = s;
        sh[t] = beta[t] - mu * s;
    }
    int cw = t & 7;
    int g  = t >> 3;
    int rowb = g * 4;
    u64 bp[4];
#pragma unroll
    for (int c = 0; c < 4; c++) bp[c] = pack2(b[cw * 8 + c * 2], b[cw * 8 + c * 2 + 1]);
    u64 zp[4] = {0, 0, 0, 0};

    const float4* Wg = (const float4*)W;
    const float4* Wng = (const float4*)Wn;
    float4* Ws4 = (float4*)Ws;

    for (int tile = 0; tile < TPB; tile++) {
        int row0 = (blockIdx.x * TPB + tile) * ROWS;
        __syncthreads();   // prior tile's Zs/Ws reads done (and sc/sh on iter 0)
        if (t < ROWS) {
            int gr = row0 + t;
            sb[t] = (gr < NN) ? batch[gr] : -1;
        }
#pragma unroll
        for (int i = 0; i < 8; i++) Ws4[t + i * GT] = Wg[t + i * GT];

        if (BN) {
            // bf16 z1 load: 64 rows x 8 chunks of 8 cols, 4 iters of 128 thr
#pragma unroll
            for (int i = 0; i < 4; i++) {
                int e = t + i * GT;
                int r = e >> 3, cb = e & 7;
                int gr = row0 + r;
                float4 w0 = make_float4(0.f, 0.f, 0.f, 0.f), w1 = w0;
                if (gr < NN) {
                    uint4 a = *(const uint4*)(g_z1b + (size_t)gr * 64 + cb * 8);
                    int k = cb * 8;
                    w0.x = fmaxf(bf_lo(a.x) * sc[k]     + sh[k],     0.f);
                    w0.y = fmaxf(bf_hi(a.x) * sc[k + 1] + sh[k + 1], 0.f);
                    w0.z = fmaxf(bf_lo(a.y) * sc[k + 2] + sh[k + 2], 0.f);
                    w0.w = fmaxf(bf_hi(a.y) * sc[k + 3] + sh[k + 3], 0.f);
                    w1.x = fmaxf(bf_lo(a.z) * sc[k + 4] + sh[k + 4], 0.f);
                    w1.y = fmaxf(bf_hi(a.z) * sc[k + 5] + sh[k + 5], 0.f);
                    w1.z = fmaxf(bf_lo(a.w) * sc[k + 6] + sh[k + 6], 0.f);
                    w1.w = fmaxf(bf_hi(a.w) * sc[k + 7] + sh[k + 7], 0.f);
                }
                float4* zr = (float4*)(Zs + r * 64);
                zr[(2 * cb + (r >> 2)) & 15]     = w0;
                zr[(2 * cb + 1 + (r >> 2)) & 15] = w1;
            }
        } else {
#pragma unroll
            for (int i = 0; i < 8; i++) {
                int e = t + i * GT;
                int r = e >> 4, c4 = e & 15;
                int gr = row0 + r;
                float4 v = make_float4(0.f, 0.f, 0.f, 0.f);
                if (gr < NN) v = ((const float4*)in)[(size_t)gr * 16 + c4];
                ((float4*)(Zs + r * 64))[(c4 + (r >> 2)) & 15] = v;
            }
        }
        __syncthreads();   // A: Zs (input) + Ws (W) ready

        {   // core 1: h = Zs @ W + b
            GEMM_CORE(bp)
            __syncthreads();   // B: all reads of Zs/Ws done
#pragma unroll
            for (int j = 0; j < 4; j++) {
                int r = rowb + j;
                int gr = row0 + r;
                float2 p0 = unpack2(acc[j][0]), p1 = unpack2(acc[j][1]);
                float2 p2 = unpack2(acc[j][2]), p3 = unpack2(acc[j][3]);
                float4 o0 = make_float4(p0.x, p0.y, p1.x, p1.y);
                float4 o1 = make_float4(p2.x, p2.y, p3.x, p3.y);
                if (gr >= NN) { o0 = make_float4(0.f, 0.f, 0.f, 0.f); o1 = o0; }
                float4* zr = (float4*)(Zs + r * 64);
                zr[(cw * 2 + g) & 15]     = o0;
                zr[(cw * 2 + 1 + g) & 15] = o1;
            }
            if (NEXT) {   // reload Ws with W1_next while Zs fills with h
#pragma unroll
                for (int i = 0; i < 8; i++) Ws4[t + i * GT] = Wng[t + i * GT];
            }
        }
        __syncthreads();   // C: Zs = h, Ws = Wn ready

        if (NEXT) {   // core 2: u = h @ Wn, bf16 out
            GEMM_CORE(zp)
#pragma unroll
            for (int j = 0; j < 4; j++) {
                int gr = row0 + rowb + j;
                if (gr < NN) {
                    float2 p0 = unpack2(acc[j][0]), p1 = unpack2(acc[j][1]);
                    float2 p2 = unpack2(acc[j][2]), p3 = unpack2(acc[j][3]);
                    __nv_bfloat162 h0 = __float22bfloat162_rn(p0);
                    __nv_bfloat162 h1 = __float22bfloat162_rn(p1);
                    __nv_bfloat162 h2 = __float22bfloat162_rn(p2);
                    __nv_bfloat162 h3 = __float22bfloat162_rn(p3);
                    uint4 u;
                    u.x = *(u32*)&h0; u.y = *(u32*)&h1;
                    u.z = *(u32*)&h2; u.w = *(u32*)&h3;
                    *(uint4*)(g_u + (size_t)gr * 64 + cw * 8) = u;
                }
            }
        }

        // segmented mean-pool over h (Zs); both halves active, 32 rows each
        {
            int col = t & 63, half = t >> 6;
            int r0 = half * 32, r1 = r0 + 32;
            float s = 0.f;
            int cur = sb[r0];
            for (int r = r0; r < r1; r++) {
                int g2 = sb[r];
                if (g2 != cur) {
                    if (cur >= 0) atomicAdd(&g_pool[cur * OUTC + pool_off + col], s);
                    s = 0.f;
                    cur = g2;
                }
                s += Zs[r * 64 + ((col + 4 * (r >> 2)) & 63)];
            }
            if (cur >= 0) atomicAdd(&g_pool[cur * OUTC + pool_off + col], s);
        }
    }
}

__global__ void finalize_kernel(float* __restrict__ out) {
    int i = blockIdx.x * 256 + threadIdx.x;
    if (i < GG * OUTC) {
        int g = i / OUTC;
        float c = (float)max(g_cnt[g], 1);
        out[i] = g_pool[i] / c;
    }
}

// ---------------- host ----------------
extern "C" void kernel_launch(void* const* d_in, const int* in_sizes, int n_in,
                              void* d_out, int out_size) {
    const float* x     = (const float*)d_in[0];
    const int*   ei    = (const int*)d_in[1];
    const int*   batch = (const int*)d_in[2];
    const float* W_emb = (const float*)d_in[3];
    const float* b_emb = (const float*)d_in[4];
    const float* W1    = (const float*)d_in[5];
    const float* b1    = (const float*)d_in[6];
    const float* gamma = (const float*)d_in[7];
    const float* beta  = (const float*)d_in[8];
    const float* W2    = (const float*)d_in[9];
    const float* b2    = (const float*)d_in[10];
    float* out = (float*)d_out;

    // persistent side-stream + events (host resources only; created once)
    static cudaStream_t sB = nullptr;
    static cudaEvent_t evFork = nullptr, evJoin = nullptr;
    if (sB == nullptr) {
        cudaStreamCreateWithFlags(&sB, cudaStreamNonBlocking);
        cudaEventCreateWithFlags(&evFork, cudaEventDisableTiming);
        cudaEventCreateWithFlags(&evJoin, cudaEventDisableTiming);
    }

    cudaFuncSetAttribute(fused_kernel<false, true>,
                         cudaFuncAttributeMaxDynamicSharedMemorySize, SMEM_G);
    cudaFuncSetAttribute(fused_kernel<true, true>,
                         cudaFuncAttributeMaxDynamicSharedMemorySize, SMEM_G);
    cudaFuncSetAttribute(fused_kernel<true, false>,
                         cudaFuncAttributeMaxDynamicSharedMemorySize, SMEM_G);

    clear_kernel<<<(NN + 255) / 256, 256>>>();

    // fork: embedding (x@W_emb+b_emb, pool, u0 = emb@W1[0]) on side stream
    cudaEventRecord(evFork, 0);
    cudaStreamWaitEvent(sB, evFork, 0);
    fused_kernel<false, true><<<GBP, GT, SMEM_G, sB>>>(x, W_emb, b_emb, W1,
                                                       nullptr, nullptr, batch, 0, 0);
    cudaEventRecord(evJoin, sB);

    // CSR build on the main stream, concurrent with the embedding
    count_deg_kernel<<<(EE + 255) / 256, 256>>>(batch, ei);
    scan1_kernel<<<NB, 1024>>>();
    scan23_kernel<<<NB, 1024>>>();
    fill_kernel<<<(EE + 255) / 256, 256>>>(ei);

    // join: layer loop needs both g_u (embedding) and g_esrc (CSR)
    cudaStreamWaitEvent(0, evJoin, 0);

    for (int l = 0; l < 4; l++) {
        gather_kernel<<<GA, 256>>>(b1 + l * 64, l);
        if (l < 3)
            fused_kernel<true, true><<<GBP, GT, SMEM_G>>>(nullptr,
                W2 + l * 4096, b2 + l * 64, W1 + (l + 1) * 4096,
                gamma + l * 64, beta + l * 64, batch, (l + 1) * 64, l);
        else
            fused_kernel<true, false><<<GBP, GT, SMEM_G>>>(nullptr,
                W2 + l * 4096, b2 + l * 64, nullptr,
                gamma + l * 64, beta + l * 64, batch, (l + 1) * 64, l);
    }

    finalize_kernel<<<(GG * OUTC + 255) / 256, 256>>>(out);
}